// round 1
// baseline (speedup 1.0000x reference)
#include <cuda_runtime.h>
#include <math.h>

#define L 512
#define D 128
#define NH 4
#define CC 32
#define M_ROWS (L * L)          // 262144
#define R_DIM (L * CC)          // 16384  (b,c) reduction size per head
#define HEAD_ELEMS (L * L * CC) // 8388608 per head

// ---------------- scratch (device globals; no allocation allowed) ----------
__device__ float g_z[M_ROWS * D];       // post-LN z, [rb, d]
__device__ float g_qt[NH * HEAD_ELEMS]; // [h, l, b, c]
__device__ float g_kt[NH * HEAD_ELEMS]; // [h, k, b, c]
__device__ float g_vt[NH * HEAD_ELEMS]; // [h, k, b, c]
__device__ float g_sig[M_ROWS * D];     // sigmoid(z@gw+gb), [rb, h*32+c]
__device__ float g_bias[M_ROWS * NH];   // [(l*512+k), h]
__device__ float g_att[NH * L * L];     // [h, l, k]
__device__ float g_o[NH * HEAD_ELEMS];  // [h, l, b, c]

// ---------------- layernorm: one warp per row --------------------------------
__global__ void ln_kernel(const float* __restrict__ zin,
                          const float* __restrict__ gamma,
                          const float* __restrict__ beta) {
    int warp = (blockIdx.x * blockDim.x + threadIdx.x) >> 5;
    int lane = threadIdx.x & 31;
    if (warp >= M_ROWS) return;
    float4 x = ((const float4*)(zin + (size_t)warp * D))[lane];
    float s = x.x + x.y + x.z + x.w;
    float ss = x.x * x.x + x.y * x.y + x.z * x.z + x.w * x.w;
    #pragma unroll
    for (int o = 16; o; o >>= 1) {
        s += __shfl_xor_sync(0xffffffffu, s, o);
        ss += __shfl_xor_sync(0xffffffffu, ss, o);
    }
    float mean = s * (1.0f / 128.0f);
    float var = ss * (1.0f / 128.0f) - mean * mean;
    float rstd = rsqrtf(var + 1e-5f);
    float4 gg = ((const float4*)gamma)[lane];
    float4 bb = ((const float4*)beta)[lane];
    float4 o;
    o.x = (x.x - mean) * rstd * gg.x + bb.x;
    o.y = (x.y - mean) * rstd * gg.y + bb.y;
    o.z = (x.z - mean) * rstd * gg.z + bb.z;
    o.w = (x.w - mean) * rstd * gg.w + bb.w;
    ((float4*)(g_z + (size_t)warp * D))[lane] = o;
}

// ---------------- projection GEMM: [262144,128] @ [128,128] ------------------
// WHICH: 0->g_qt (transposed), 1->g_kt, 2->g_vt, 3->g_sig (natural + sigmoid)
template <int WHICH>
__global__ void proj_kernel(const float* __restrict__ W,
                            const float* __restrict__ bias) {
    __shared__ float As[16][68];
    __shared__ float Bs[16][68];
    int tid = threadIdx.x;
    int tx = tid & 15, ty = tid >> 4;
    int bm0 = blockIdx.y * 64;
    int bn0 = blockIdx.x * 64;
    float acc[4][4] = {};
    for (int k0 = 0; k0 < 128; k0 += 16) {
        {
            int r = tid >> 2;
            int kq = (tid & 3) * 4;
            float4 v = *(const float4*)(g_z + (size_t)(bm0 + r) * 128 + k0 + kq);
            As[kq + 0][r] = v.x; As[kq + 1][r] = v.y;
            As[kq + 2][r] = v.z; As[kq + 3][r] = v.w;
        }
        {
            int r = tid >> 4;
            int c = (tid & 15) * 4;
            float4 v = *(const float4*)(W + (size_t)(k0 + r) * 128 + bn0 + c);
            *(float4*)&Bs[r][c] = v;
        }
        __syncthreads();
        #pragma unroll
        for (int kk = 0; kk < 16; kk++) {
            float4 a = *(const float4*)&As[kk][ty * 4];
            float4 b = *(const float4*)&Bs[kk][tx * 4];
            float av[4] = {a.x, a.y, a.z, a.w};
            float bv[4] = {b.x, b.y, b.z, b.w};
            #pragma unroll
            for (int i = 0; i < 4; i++)
                #pragma unroll
                for (int j = 0; j < 4; j++) acc[i][j] += av[i] * bv[j];
        }
        __syncthreads();
    }
    float* outp = (WHICH == 0) ? g_qt : (WHICH == 1) ? g_kt : (WHICH == 2) ? g_vt : g_sig;
    #pragma unroll
    for (int i = 0; i < 4; i++) {
        int rb = bm0 + ty * 4 + i;
        int bidx = rb >> 9, l = rb & 511;
        #pragma unroll
        for (int j = 0; j < 4; j++) {
            int n = bn0 + tx * 4 + j;
            float v = acc[i][j] + bias[n];
            if (WHICH <= 2) {
                int h = n >> 5, c = n & 31;
                outp[(((size_t)h * L + l) * L + bidx) * CC + c] = v;
            } else {
                outp[(size_t)rb * 128 + n] = 1.0f / (1.0f + expf(-v));
            }
        }
    }
}

// ---------------- bias projection: [262144,128] @ [128,4], warp per row ------
__global__ void biasproj_kernel(const float* __restrict__ bw,
                                const float* __restrict__ bb) {
    int warp = (blockIdx.x * blockDim.x + threadIdx.x) >> 5;
    int lane = threadIdx.x & 31;
    if (warp >= M_ROWS) return;
    const float* zr = g_z + (size_t)warp * 128;
    float a0 = 0, a1 = 0, a2 = 0, a3 = 0;
    #pragma unroll
    for (int i = lane; i < 128; i += 32) {
        float x = zr[i];
        float4 w = *(const float4*)(bw + i * 4);
        a0 += x * w.x; a1 += x * w.y; a2 += x * w.z; a3 += x * w.w;
    }
    #pragma unroll
    for (int o = 16; o; o >>= 1) {
        a0 += __shfl_xor_sync(0xffffffffu, a0, o);
        a1 += __shfl_xor_sync(0xffffffffu, a1, o);
        a2 += __shfl_xor_sync(0xffffffffu, a2, o);
        a3 += __shfl_xor_sync(0xffffffffu, a3, o);
    }
    if (lane == 0) {
        float* p = g_bias + (size_t)warp * 4;
        p[0] = a0 + bb[0]; p[1] = a1 + bb[1];
        p[2] = a2 + bb[2]; p[3] = a3 + bb[3];
    }
}

// ---------------- logits: per head [512,16384] @ [512,16384]^T (NT) ----------
__global__ void att_kernel(float scale) {
    __shared__ float As[16][68];
    __shared__ float Bs[16][68];
    int tid = threadIdx.x;
    int tx = tid & 15, ty = tid >> 4;
    int h = blockIdx.z;
    int bm0 = blockIdx.y * 64;  // l
    int bn0 = blockIdx.x * 64;  // k position
    const float* Ah = g_qt + (size_t)h * HEAD_ELEMS;
    const float* Bh = g_kt + (size_t)h * HEAD_ELEMS;
    float acc[4][4] = {};
    for (int k0 = 0; k0 < R_DIM; k0 += 16) {
        int r = tid >> 2;
        int kq = (tid & 3) * 4;
        float4 va = *(const float4*)(Ah + (size_t)(bm0 + r) * R_DIM + k0 + kq);
        As[kq + 0][r] = va.x; As[kq + 1][r] = va.y;
        As[kq + 2][r] = va.z; As[kq + 3][r] = va.w;
        float4 vb = *(const float4*)(Bh + (size_t)(bn0 + r) * R_DIM + k0 + kq);
        Bs[kq + 0][r] = vb.x; Bs[kq + 1][r] = vb.y;
        Bs[kq + 2][r] = vb.z; Bs[kq + 3][r] = vb.w;
        __syncthreads();
        #pragma unroll
        for (int kk = 0; kk < 16; kk++) {
            float4 a = *(const float4*)&As[kk][ty * 4];
            float4 b = *(const float4*)&Bs[kk][tx * 4];
            float av[4] = {a.x, a.y, a.z, a.w};
            float bv[4] = {b.x, b.y, b.z, b.w};
            #pragma unroll
            for (int i = 0; i < 4; i++)
                #pragma unroll
                for (int j = 0; j < 4; j++) acc[i][j] += av[i] * bv[j];
        }
        __syncthreads();
    }
    #pragma unroll
    for (int i = 0; i < 4; i++) {
        int lpos = bm0 + ty * 4 + i;
        #pragma unroll
        for (int j = 0; j < 4; j++) {
            int kpos = bn0 + tx * 4 + j;
            g_att[((size_t)h * L + lpos) * L + kpos] =
                acc[i][j] * scale + g_bias[((size_t)lpos * L + kpos) * NH + h];
        }
    }
}

// ---------------- softmax over k: one block (128 thr) per (h,l) row ----------
__global__ void softmax_kernel() {
    __shared__ float red[4];
    int row = blockIdx.x;
    float* p = g_att + (size_t)row * L;
    int t = threadIdx.x;
    int warp = t >> 5, lane = t & 31;
    float4 x = ((float4*)p)[t];
    float m = fmaxf(fmaxf(x.x, x.y), fmaxf(x.z, x.w));
    #pragma unroll
    for (int o = 16; o; o >>= 1) m = fmaxf(m, __shfl_xor_sync(0xffffffffu, m, o));
    if (lane == 0) red[warp] = m;
    __syncthreads();
    m = fmaxf(fmaxf(red[0], red[1]), fmaxf(red[2], red[3]));
    __syncthreads();
    x.x = expf(x.x - m); x.y = expf(x.y - m);
    x.z = expf(x.z - m); x.w = expf(x.w - m);
    float s = x.x + x.y + x.z + x.w;
    #pragma unroll
    for (int o = 16; o; o >>= 1) s += __shfl_xor_sync(0xffffffffu, s, o);
    if (lane == 0) red[warp] = s;
    __syncthreads();
    s = red[0] + red[1] + red[2] + red[3];
    float inv = 1.0f / s;
    x.x *= inv; x.y *= inv; x.z *= inv; x.w *= inv;
    ((float4*)p)[t] = x;
}

// ---------------- O: per head [512,512] @ [512,16384] (NN) -------------------
__global__ void o_kernel() {
    __shared__ float As[16][68];
    __shared__ float Bs[16][68];
    int tid = threadIdx.x;
    int tx = tid & 15, ty = tid >> 4;
    int h = blockIdx.z;
    int bm0 = blockIdx.y * 64;  // l
    int bn0 = blockIdx.x * 64;  // n = b*32+c
    const float* Ah = g_att + (size_t)h * L * L;
    const float* Bh = g_vt + (size_t)h * HEAD_ELEMS;
    float acc[4][4] = {};
    for (int k0 = 0; k0 < L; k0 += 16) {
        {
            int r = tid >> 2;
            int kq = (tid & 3) * 4;
            float4 va = *(const float4*)(Ah + (size_t)(bm0 + r) * L + k0 + kq);
            As[kq + 0][r] = va.x; As[kq + 1][r] = va.y;
            As[kq + 2][r] = va.z; As[kq + 3][r] = va.w;
        }
        {
            int r = tid >> 4;
            int c = (tid & 15) * 4;
            float4 vb = *(const float4*)(Bh + (size_t)(k0 + r) * R_DIM + bn0 + c);
            *(float4*)&Bs[r][c] = vb;
        }
        __syncthreads();
        #pragma unroll
        for (int kk = 0; kk < 16; kk++) {
            float4 a = *(const float4*)&As[kk][ty * 4];
            float4 b = *(const float4*)&Bs[kk][tx * 4];
            float av[4] = {a.x, a.y, a.z, a.w};
            float bv[4] = {b.x, b.y, b.z, b.w};
            #pragma unroll
            for (int i = 0; i < 4; i++)
                #pragma unroll
                for (int j = 0; j < 4; j++) acc[i][j] += av[i] * bv[j];
        }
        __syncthreads();
    }
    float* outp = g_o + (size_t)h * HEAD_ELEMS;
    #pragma unroll
    for (int i = 0; i < 4; i++) {
        int lpos = bm0 + ty * 4 + i;
        #pragma unroll
        for (int j = 0; j < 4; j++)
            outp[(size_t)lpos * R_DIM + bn0 + tx * 4 + j] = acc[i][j];
    }
}

// ---------------- final: gather+gate, [262144,128] @ [128,128] + ob ----------
__global__ void out_kernel(const float* __restrict__ ow,
                           const float* __restrict__ ob,
                           float* __restrict__ out) {
    __shared__ float As[16][68];
    __shared__ float Bs[16][68];
    int tid = threadIdx.x;
    int tx = tid & 15, ty = tid >> 4;
    int bm0 = blockIdx.y * 64;
    int bn0 = blockIdx.x * 64;
    float acc[4][4] = {};
    for (int k0 = 0; k0 < 128; k0 += 16) {
        {
            int r = tid >> 2;
            int kq = (tid & 3) * 4;
            int rb = bm0 + r;
            int bidx = rb >> 9, l = rb & 511;
            int n = k0 + kq;
            int h = n >> 5, c = n & 31;
            float4 ov = *(const float4*)(g_o + (size_t)h * HEAD_ELEMS +
                                         (size_t)l * R_DIM + bidx * CC + c);
            float4 sv = *(const float4*)(g_sig + (size_t)rb * 128 + n);
            As[kq + 0][r] = ov.x * sv.x; As[kq + 1][r] = ov.y * sv.y;
            As[kq + 2][r] = ov.z * sv.z; As[kq + 3][r] = ov.w * sv.w;
        }
        {
            int r = tid >> 4;
            int c = (tid & 15) * 4;
            float4 v = *(const float4*)(ow + (size_t)(k0 + r) * 128 + bn0 + c);
            *(float4*)&Bs[r][c] = v;
        }
        __syncthreads();
        #pragma unroll
        for (int kk = 0; kk < 16; kk++) {
            float4 a = *(const float4*)&As[kk][ty * 4];
            float4 b = *(const float4*)&Bs[kk][tx * 4];
            float av[4] = {a.x, a.y, a.z, a.w};
            float bv[4] = {b.x, b.y, b.z, b.w};
            #pragma unroll
            for (int i = 0; i < 4; i++)
                #pragma unroll
                for (int j = 0; j < 4; j++) acc[i][j] += av[i] * bv[j];
        }
        __syncthreads();
    }
    #pragma unroll
    for (int i = 0; i < 4; i++) {
        int rb = bm0 + ty * 4 + i;
        #pragma unroll
        for (int j = 0; j < 4; j++) {
            int n = bn0 + tx * 4 + j;
            out[(size_t)rb * 128 + n] = acc[i][j] + ob[n];
        }
    }
}

// ---------------- launcher ---------------------------------------------------
extern "C" void kernel_launch(void* const* d_in, const int* in_sizes, int n_in,
                              void* d_out, int out_size) {
    const float* z_   = (const float*)d_in[0];
    const float* ln_g = (const float*)d_in[1];
    const float* ln_b = (const float*)d_in[2];
    const float* qw   = (const float*)d_in[3];
    const float* qb   = (const float*)d_in[4];
    const float* kw   = (const float*)d_in[5];
    const float* kb   = (const float*)d_in[6];
    const float* vw   = (const float*)d_in[7];
    const float* vb   = (const float*)d_in[8];
    const float* bw   = (const float*)d_in[9];
    const float* bb   = (const float*)d_in[10];
    const float* gw   = (const float*)d_in[11];
    const float* gb   = (const float*)d_in[12];
    const float* ow   = (const float*)d_in[13];
    const float* ob   = (const float*)d_in[14];
    float* out = (float*)d_out;

    ln_kernel<<<M_ROWS / 8, 256>>>(z_, ln_g, ln_b);

    dim3 pgrid(2, M_ROWS / 64);
    proj_kernel<0><<<pgrid, 256>>>(qw, qb);
    proj_kernel<1><<<pgrid, 256>>>(kw, kb);
    proj_kernel<2><<<pgrid, 256>>>(vw, vb);
    proj_kernel<3><<<pgrid, 256>>>(gw, gb);
    biasproj_kernel<<<M_ROWS / 8, 256>>>(bw, bb);

    float scale = 1.0f / (sqrtf((float)CC) * sqrtf((float)L));
    att_kernel<<<dim3(8, 8, NH), 256>>>(scale);

    softmax_kernel<<<NH * L, 128>>>();

    o_kernel<<<dim3(R_DIM / 64, 8, NH), 256>>>();

    out_kernel<<<dim3(2, M_ROWS / 64), 256>>>(ow, ob, out);
}

// round 2
// speedup vs baseline: 2.9878x; 2.9878x over previous
#include <cuda_runtime.h>
#include <math.h>

#define L 512
#define D 128
#define NH 4
#define CC 32
#define M_ROWS (L * L)          // 262144
#define R_DIM (L * CC)          // 16384
#define HEAD_ELEMS (L * L * CC)

// ---------------- scratch ----------------------------------------------------
__device__ float g_z[M_ROWS * D];        // post-LN z, [rb, d]
__device__ float g_qT[NH * R_DIM * L];   // [h][bc][l]
__device__ float g_kT[NH * R_DIM * L];   // [h][bc][l]
__device__ float g_vt[NH * L * R_DIM];   // [h][k2][bc]
__device__ float g_sig[M_ROWS * D];      // sigmoid(z@gw+gb)
__device__ float g_bias[M_ROWS * NH];    // [(l*512+k), h]
__device__ float g_part[16 * L * L];     // [h*4+sk][l][k] split-K partials
__device__ float g_att[NH * L * L];      // [h][l][k] softmax probs
__device__ float g_o[NH * L * R_DIM];    // [h][l][bc]

// ---------------- tf32 mma helpers -------------------------------------------
__device__ __forceinline__ unsigned tf32c(float x) {
    unsigned u; asm("cvt.rna.tf32.f32 %0, %1;" : "=r"(u) : "f"(x)); return u;
}

__device__ __forceinline__ void mma8(float* c, const unsigned* a, const unsigned* b) {
    asm volatile(
        "mma.sync.aligned.m16n8k8.row.col.f32.tf32.tf32.f32 "
        "{%0,%1,%2,%3},{%4,%5,%6,%7},{%8,%9},{%0,%1,%2,%3};"
        : "+f"(c[0]), "+f"(c[1]), "+f"(c[2]), "+f"(c[3])
        : "r"(a[0]), "r"(a[1]), "r"(a[2]), "r"(a[3]), "r"(b[0]), "r"(b[1]));
}

// smem tiles are [k=16][dim=128 + pad to 136]; frag loads are bank-conflict-free.
__device__ __forceinline__ void compute_tile(
    const unsigned (*As)[136], const unsigned (*Bs)[136],
    float acc[4][4][4], int wr, int wc, int lane)
{
    int t = lane & 3, g = lane >> 2;
    #pragma unroll
    for (int ks = 0; ks < 16; ks += 8) {
        unsigned a[4][4], b[4][2];
        #pragma unroll
        for (int mi = 0; mi < 4; mi++) {
            int r = wr * 64 + mi * 16 + g;
            a[mi][0] = As[ks + t][r];
            a[mi][1] = As[ks + t][r + 8];
            a[mi][2] = As[ks + t + 4][r];
            a[mi][3] = As[ks + t + 4][r + 8];
        }
        #pragma unroll
        for (int ni = 0; ni < 4; ni++) {
            int c = wc * 32 + ni * 8 + g;
            b[ni][0] = Bs[ks + t][c];
            b[ni][1] = Bs[ks + t + 4][c];
        }
        #pragma unroll
        for (int mi = 0; mi < 4; mi++)
            #pragma unroll
            for (int ni = 0; ni < 4; ni++)
                mma8(acc[mi][ni], a[mi], b[ni]);
    }
}

// load 128 rows x 16 k from row-major [row][k] (src pre-offset), transpose to S[k][row]
__device__ __forceinline__ void load_trans(unsigned (*S)[136], const float* src,
                                           size_t ld, int tid) {
    #pragma unroll
    for (int i = 0; i < 2; i++) {
        int r = (tid >> 2) + i * 64;
        int k4 = (tid & 3) * 4;
        float4 v = *(const float4*)(src + (size_t)r * ld + k4);
        S[k4 + 0][r] = tf32c(v.x);
        S[k4 + 1][r] = tf32c(v.y);
        S[k4 + 2][r] = tf32c(v.z);
        S[k4 + 3][r] = tf32c(v.w);
    }
}

// load 16 k-rows x 128 cols from row-major [k][col] (src pre-offset) directly
__device__ __forceinline__ void load_direct(unsigned (*S)[136], const float* src,
                                            size_t ld, int tid) {
    #pragma unroll
    for (int i = 0; i < 2; i++) {
        int k = (tid >> 5) + i * 8;
        int n4 = (tid & 31) * 4;
        float4 v = *(const float4*)(src + (size_t)k * ld + n4);
        uint4 u;
        u.x = tf32c(v.x); u.y = tf32c(v.y); u.z = tf32c(v.z); u.w = tf32c(v.w);
        *(uint4*)&S[k][n4] = u;
    }
}

// ---------------- layernorm --------------------------------------------------
__global__ void ln_kernel(const float* __restrict__ zin,
                          const float* __restrict__ gamma,
                          const float* __restrict__ beta) {
    int warp = (blockIdx.x * blockDim.x + threadIdx.x) >> 5;
    int lane = threadIdx.x & 31;
    if (warp >= M_ROWS) return;
    float4 x = ((const float4*)(zin + (size_t)warp * D))[lane];
    float s = x.x + x.y + x.z + x.w;
    float ss = x.x * x.x + x.y * x.y + x.z * x.z + x.w * x.w;
    #pragma unroll
    for (int o = 16; o; o >>= 1) {
        s += __shfl_xor_sync(0xffffffffu, s, o);
        ss += __shfl_xor_sync(0xffffffffu, ss, o);
    }
    float mean = s * (1.0f / 128.0f);
    float var = ss * (1.0f / 128.0f) - mean * mean;
    float rstd = rsqrtf(var + 1e-5f);
    float4 gg = ((const float4*)gamma)[lane];
    float4 bb = ((const float4*)beta)[lane];
    float4 o;
    o.x = (x.x - mean) * rstd * gg.x + bb.x;
    o.y = (x.y - mean) * rstd * gg.y + bb.y;
    o.z = (x.z - mean) * rstd * gg.z + bb.z;
    o.w = (x.w - mean) * rstd * gg.w + bb.w;
    ((float4*)(g_z + (size_t)warp * D))[lane] = o;
}

// ---------------- bias projection: warp per row ------------------------------
__global__ void biasproj_kernel(const float* __restrict__ bw,
                                const float* __restrict__ bb) {
    int warp = (blockIdx.x * blockDim.x + threadIdx.x) >> 5;
    int lane = threadIdx.x & 31;
    if (warp >= M_ROWS) return;
    const float* zr = g_z + (size_t)warp * 128;
    float a0 = 0, a1 = 0, a2 = 0, a3 = 0;
    #pragma unroll
    for (int i = lane; i < 128; i += 32) {
        float x = zr[i];
        float4 w = *(const float4*)(bw + i * 4);
        a0 += x * w.x; a1 += x * w.y; a2 += x * w.z; a3 += x * w.w;
    }
    #pragma unroll
    for (int o = 16; o; o >>= 1) {
        a0 += __shfl_xor_sync(0xffffffffu, a0, o);
        a1 += __shfl_xor_sync(0xffffffffu, a1, o);
        a2 += __shfl_xor_sync(0xffffffffu, a2, o);
        a3 += __shfl_xor_sync(0xffffffffu, a3, o);
    }
    if (lane == 0) {
        float* p = g_bias + (size_t)warp * 4;
        p[0] = a0 + bb[0]; p[1] = a1 + bb[1];
        p[2] = a2 + bb[2]; p[3] = a3 + bb[3];
    }
}

// ---------------- fused q/k/v/g projections (tf32 mma) -----------------------
// grid (4, 2048): x = which weight, y = m-block
__global__ void __launch_bounds__(256, 2) proj_mma(
    const float* __restrict__ qw, const float* __restrict__ qb,
    const float* __restrict__ kw, const float* __restrict__ kb,
    const float* __restrict__ vw, const float* __restrict__ vb,
    const float* __restrict__ gw, const float* __restrict__ gb)
{
    __shared__ unsigned As[16][136];
    __shared__ unsigned Bs[16][136];
    __shared__ float Stage[4608];
    int which = blockIdx.x;
    int m0 = blockIdx.y * 128;
    const float* W = which == 0 ? qw : which == 1 ? kw : which == 2 ? vw : gw;
    const float* Bv = which == 0 ? qb : which == 1 ? kb : which == 2 ? vb : gb;
    int tid = threadIdx.x, lane = tid & 31, wid = tid >> 5;
    int wr = wid >> 2, wc = wid & 3;
    float acc[4][4][4] = {};
    for (int kt = 0; kt < 128; kt += 16) {
        load_trans(As, g_z + (size_t)m0 * 128 + kt, 128, tid);
        load_direct(Bs, W + (size_t)kt * 128, 128, tid);
        __syncthreads();
        compute_tile(As, Bs, acc, wr, wc, lane);
        __syncthreads();
    }
    int t = lane & 3, g = lane >> 2;
    int b = m0 >> 9;
    int l0 = m0 & 511;
    if (which < 2) {
        // q/k: write [h][bc][l] coalesced along l, staged via smem transposed
        float* dst = (which == 0) ? g_qT : g_kT;
        float (*S2)[132] = (float(*)[132])Stage;
        for (int j = 0; j < 4; j++) {   // head chunk
            __syncthreads();
            if (wc == j) {
                #pragma unroll
                for (int mi = 0; mi < 4; mi++) {
                    int r = wr * 64 + mi * 16 + g;
                    #pragma unroll
                    for (int ni = 0; ni < 4; ni++) {
                        int c = ni * 8 + t * 2;
                        float b0 = Bv[j * 32 + c], b1 = Bv[j * 32 + c + 1];
                        S2[c][r] = acc[mi][ni][0] + b0;
                        S2[c + 1][r] = acc[mi][ni][1] + b1;
                        S2[c][r + 8] = acc[mi][ni][2] + b0;
                        S2[c + 1][r + 8] = acc[mi][ni][3] + b1;
                    }
                }
            }
            __syncthreads();
            #pragma unroll
            for (int pass = 0; pass < 4; pass++) {
                int c = wid + pass * 8;
                int l4 = lane * 4;
                float4 v = *(float4*)&S2[c][l4];
                *(float4*)(dst + ((size_t)j * R_DIM + b * 32 + c) * 512 + l0 + l4) = v;
            }
        }
    } else if (which == 2) {
        // v: write [h][k2][bc] coalesced along bc, staged via smem
        float (*S1)[36] = (float(*)[36])Stage;
        for (int j = 0; j < 4; j++) {
            __syncthreads();
            if (wc == j) {
                #pragma unroll
                for (int mi = 0; mi < 4; mi++) {
                    int r = wr * 64 + mi * 16 + g;
                    #pragma unroll
                    for (int ni = 0; ni < 4; ni++) {
                        int c = ni * 8 + t * 2;
                        float b0 = Bv[j * 32 + c], b1 = Bv[j * 32 + c + 1];
                        S1[r][c] = acc[mi][ni][0] + b0;
                        S1[r][c + 1] = acc[mi][ni][1] + b1;
                        S1[r + 8][c] = acc[mi][ni][2] + b0;
                        S1[r + 8][c + 1] = acc[mi][ni][3] + b1;
                    }
                }
            }
            __syncthreads();
            #pragma unroll
            for (int pass = 0; pass < 4; pass++) {
                int row = (tid >> 3) + pass * 32;
                int c4 = (tid & 7) * 4;
                float4 v = *(float4*)&S1[row][c4];
                *(float4*)(g_vt + ((size_t)j * 512 + l0 + row) * R_DIM + b * 32 + c4) = v;
            }
        }
    } else {
        // gate: sigmoid, natural row-major layout (float2 = full 32B sectors)
        #pragma unroll
        for (int mi = 0; mi < 4; mi++) {
            int r0 = m0 + wr * 64 + mi * 16 + g;
            #pragma unroll
            for (int ni = 0; ni < 4; ni++) {
                int c = wc * 32 + ni * 8 + t * 2;
                float b0 = Bv[c], b1 = Bv[c + 1];
                float2 v0 = make_float2(1.f / (1.f + __expf(-(acc[mi][ni][0] + b0))),
                                        1.f / (1.f + __expf(-(acc[mi][ni][1] + b1))));
                float2 v1 = make_float2(1.f / (1.f + __expf(-(acc[mi][ni][2] + b0))),
                                        1.f / (1.f + __expf(-(acc[mi][ni][3] + b1))));
                *(float2*)(g_sig + (size_t)r0 * 128 + c) = v0;
                *(float2*)(g_sig + (size_t)(r0 + 8) * 128 + c) = v1;
            }
        }
    }
}

// ---------------- logits: per head, split-K=4 --------------------------------
// grid (4, 4, 16): x = k-block, y = l-block, z = h*4+sk
__global__ void __launch_bounds__(256, 2) att_mma() {
    __shared__ unsigned As[16][136];
    __shared__ unsigned Bs[16][136];
    int n0 = blockIdx.x * 128, m0 = blockIdx.y * 128;
    int h = blockIdx.z >> 2, sk = blockIdx.z & 3;
    const float* Aq = g_qT + (size_t)h * R_DIM * 512;
    const float* Bk = g_kT + (size_t)h * R_DIM * 512;
    int tid = threadIdx.x, lane = tid & 31, wid = tid >> 5;
    int wr = wid >> 2, wc = wid & 3;
    float acc[4][4][4] = {};
    int kbeg = sk * 4096, kend = kbeg + 4096;
    for (int kt = kbeg; kt < kend; kt += 16) {
        load_direct(As, Aq + (size_t)kt * 512 + m0, 512, tid);
        load_direct(Bs, Bk + (size_t)kt * 512 + n0, 512, tid);
        __syncthreads();
        compute_tile(As, Bs, acc, wr, wc, lane);
        __syncthreads();
    }
    int t = lane & 3, g = lane >> 2;
    float* outp = g_part + (size_t)blockIdx.z * (L * L);
    #pragma unroll
    for (int mi = 0; mi < 4; mi++) {
        int l = m0 + wr * 64 + mi * 16 + g;
        #pragma unroll
        for (int ni = 0; ni < 4; ni++) {
            int k = n0 + wc * 32 + ni * 8 + t * 2;
            *(float2*)(outp + (size_t)l * 512 + k) =
                make_float2(acc[mi][ni][0], acc[mi][ni][1]);
            *(float2*)(outp + (size_t)(l + 8) * 512 + k) =
                make_float2(acc[mi][ni][2], acc[mi][ni][3]);
        }
    }
}

// ---------------- split-K reduce + scale + bias + softmax --------------------
__global__ void softmax2(float scale) {
    __shared__ float red[4];
    int h = blockIdx.x >> 9, l = blockIdx.x & 511;
    int tth = threadIdx.x;
    int warp = tth >> 5, lane = tth & 31;
    int k = tth * 4;
    float4 x = make_float4(0.f, 0.f, 0.f, 0.f);
    #pragma unroll
    for (int sk = 0; sk < 4; sk++) {
        const float4 p = *(const float4*)(g_part +
            ((size_t)(h * 4 + sk) * 512 + l) * 512 + k);
        x.x += p.x; x.y += p.y; x.z += p.z; x.w += p.w;
    }
    const float* bp = g_bias + ((size_t)l * 512 + k) * 4 + h;
    x.x = x.x * scale + bp[0];
    x.y = x.y * scale + bp[4];
    x.z = x.z * scale + bp[8];
    x.w = x.w * scale + bp[12];
    float m = fmaxf(fmaxf(x.x, x.y), fmaxf(x.z, x.w));
    #pragma unroll
    for (int o = 16; o; o >>= 1) m = fmaxf(m, __shfl_xor_sync(0xffffffffu, m, o));
    if (lane == 0) red[warp] = m;
    __syncthreads();
    m = fmaxf(fmaxf(red[0], red[1]), fmaxf(red[2], red[3]));
    __syncthreads();
    x.x = expf(x.x - m); x.y = expf(x.y - m);
    x.z = expf(x.z - m); x.w = expf(x.w - m);
    float s = x.x + x.y + x.z + x.w;
    #pragma unroll
    for (int o = 16; o; o >>= 1) s += __shfl_xor_sync(0xffffffffu, s, o);
    if (lane == 0) red[warp] = s;
    __syncthreads();
    s = red[0] + red[1] + red[2] + red[3];
    float inv = 1.0f / s;
    x.x *= inv; x.y *= inv; x.z *= inv; x.w *= inv;
    *(float4*)(g_att + ((size_t)(h * 512 + l)) * 512 + k) = x;
}

// ---------------- O = att @ V (tf32 mma) -------------------------------------
// grid (128, 4, 4): x = bc-block, y = l-block, z = head
__global__ void __launch_bounds__(256, 2) o_mma() {
    __shared__ unsigned As[16][136];
    __shared__ unsigned Bs[16][136];
    int n0 = blockIdx.x * 128, m0 = blockIdx.y * 128, h = blockIdx.z;
    int tid = threadIdx.x, lane = tid & 31, wid = tid >> 5;
    int wr = wid >> 2, wc = wid & 3;
    const float* Aa = g_att + (size_t)h * (L * L);
    const float* Bv = g_vt + (size_t)h * L * R_DIM;
    float acc[4][4][4] = {};
    for (int kt = 0; kt < 512; kt += 16) {
        load_trans(As, Aa + (size_t)m0 * 512 + kt, 512, tid);
        load_direct(Bs, Bv + (size_t)kt * R_DIM + n0, R_DIM, tid);
        __syncthreads();
        compute_tile(As, Bs, acc, wr, wc, lane);
        __syncthreads();
    }
    int t = lane & 3, g = lane >> 2;
    float* outp = g_o + (size_t)h * L * R_DIM;
    #pragma unroll
    for (int mi = 0; mi < 4; mi++) {
        int l = m0 + wr * 64 + mi * 16 + g;
        #pragma unroll
        for (int ni = 0; ni < 4; ni++) {
            int n = n0 + wc * 32 + ni * 8 + t * 2;
            *(float2*)(outp + (size_t)l * R_DIM + n) =
                make_float2(acc[mi][ni][0], acc[mi][ni][1]);
            *(float2*)(outp + (size_t)(l + 8) * R_DIM + n) =
                make_float2(acc[mi][ni][2], acc[mi][ni][3]);
        }
    }
}

// ---------------- final: gate * o, project by ow, + ob -----------------------
// grid (2048): m-blocks
__global__ void __launch_bounds__(256, 2) out_mma(const float* __restrict__ ow,
                                                  const float* __restrict__ ob,
                                                  float* __restrict__ out) {
    __shared__ unsigned As[16][136];
    __shared__ unsigned Bs[16][136];
    int m0 = blockIdx.x * 128;
    int tid = threadIdx.x, lane = tid & 31, wid = tid >> 5;
    int wr = wid >> 2, wc = wid & 3;
    float acc[4][4][4] = {};
    for (int kt = 0; kt < 128; kt += 16) {
        // gather g_o (by head layout) * g_sig, transpose into As
        #pragma unroll
        for (int i = 0; i < 2; i++) {
            int r = (tid >> 2) + i * 64;
            int rb = m0 + r;
            int b = rb >> 9, l = rb & 511;
            int k4 = (tid & 3) * 4;
            int n = kt + k4;
            int hh = n >> 5, c = n & 31;
            float4 vo = *(const float4*)(g_o + ((size_t)hh * 512 + l) * R_DIM + b * 32 + c);
            float4 vs = *(const float4*)(g_sig + (size_t)rb * 128 + n);
            As[k4 + 0][r] = tf32c(vo.x * vs.x);
            As[k4 + 1][r] = tf32c(vo.y * vs.y);
            As[k4 + 2][r] = tf32c(vo.z * vs.z);
            As[k4 + 3][r] = tf32c(vo.w * vs.w);
        }
        load_direct(Bs, ow + (size_t)kt * 128, 128, tid);
        __syncthreads();
        compute_tile(As, Bs, acc, wr, wc, lane);
        __syncthreads();
    }
    int t = lane & 3, g = lane >> 2;
    #pragma unroll
    for (int mi = 0; mi < 4; mi++) {
        int r0 = m0 + wr * 64 + mi * 16 + g;
        #pragma unroll
        for (int ni = 0; ni < 4; ni++) {
            int c = wc * 32 + ni * 8 + t * 2;
            float b0 = ob[c], b1 = ob[c + 1];
            *(float2*)(out + (size_t)r0 * 128 + c) =
                make_float2(acc[mi][ni][0] + b0, acc[mi][ni][1] + b1);
            *(float2*)(out + (size_t)(r0 + 8) * 128 + c) =
                make_float2(acc[mi][ni][2] + b0, acc[mi][ni][3] + b1);
        }
    }
}

// ---------------- launcher ---------------------------------------------------
extern "C" void kernel_launch(void* const* d_in, const int* in_sizes, int n_in,
                              void* d_out, int out_size) {
    const float* z_   = (const float*)d_in[0];
    const float* ln_g = (const float*)d_in[1];
    const float* ln_b = (const float*)d_in[2];
    const float* qw   = (const float*)d_in[3];
    const float* qb   = (const float*)d_in[4];
    const float* kw   = (const float*)d_in[5];
    const float* kb   = (const float*)d_in[6];
    const float* vw   = (const float*)d_in[7];
    const float* vb   = (const float*)d_in[8];
    const float* bw   = (const float*)d_in[9];
    const float* bb   = (const float*)d_in[10];
    const float* gw   = (const float*)d_in[11];
    const float* gb   = (const float*)d_in[12];
    const float* ow   = (const float*)d_in[13];
    const float* ob   = (const float*)d_in[14];
    float* out = (float*)d_out;

    ln_kernel<<<M_ROWS / 8, 256>>>(z_, ln_g, ln_b);
    biasproj_kernel<<<M_ROWS / 8, 256>>>(bw, bb);
    proj_mma<<<dim3(4, 2048), 256>>>(qw, qb, kw, kb, vw, vb, gw, gb);

    float scale = 1.0f / (sqrtf((float)CC) * sqrtf((float)L));
    att_mma<<<dim3(4, 4, 16), 256>>>();
    softmax2<<<NH * L, 128>>>(scale);
    o_mma<<<dim3(128, 4, 4), 256>>>();
    out_mma<<<2048, 256>>>(ow, ob, out);
}

// round 5
// speedup vs baseline: 3.4561x; 1.1567x over previous
#include <cuda_runtime.h>
#include <stdint.h>
#include <math.h>

#define L 512
#define D 128
#define NH 4
#define CC 32
#define M_ROWS (L * L)          // 262144
#define R_DIM (L * CC)          // 16384
#define LL (L * L)

// ---------------- scratch ----------------------------------------------------
__device__ float g_z[M_ROWS * D];        // post-LN z (tf32-rounded), [rb, d]
__device__ float g_qT[NH * R_DIM * L];   // [h][bc][l] tf32-rounded
__device__ float g_kT[NH * R_DIM * L];   // [h][bc][l] tf32-rounded
__device__ float g_vt[NH * L * R_DIM];   // [h][k2][bc] tf32-rounded
__device__ float g_sig[M_ROWS * D];      // sigmoid(z@gw+gb)
__device__ float g_bias[M_ROWS * NH];    // [(l*512+k), h]
__device__ float g_part[32 * LL];        // [h*8+sk][l][k] split-K partials
__device__ float g_att[NH * LL];         // [h][l][k] softmax probs (tf32-rounded)
__device__ float g_o[NH * L * R_DIM];    // [h][l][bc]
__device__ float g_wq[D * D], g_wk[D * D], g_wv[D * D], g_wg[D * D]; // tf32 weights

// ---------------- helpers ----------------------------------------------------
__device__ __forceinline__ unsigned tf32c(float x) {
    unsigned u; asm("cvt.rna.tf32.f32 %0, %1;" : "=r"(u) : "f"(x)); return u;
}
__device__ __forceinline__ float tf32f(float x) { return __uint_as_float(tf32c(x)); }

__device__ __forceinline__ void mma8(float* c, const unsigned* a, const unsigned* b) {
    asm volatile(
        "mma.sync.aligned.m16n8k8.row.col.f32.tf32.tf32.f32 "
        "{%0,%1,%2,%3},{%4,%5,%6,%7},{%8,%9},{%0,%1,%2,%3};"
        : "+f"(c[0]), "+f"(c[1]), "+f"(c[2]), "+f"(c[3])
        : "r"(a[0]), "r"(a[1]), "r"(a[2]), "r"(a[3]), "r"(b[0]), "r"(b[1]));
}

__device__ __forceinline__ void cpa16(uint32_t dst, const float* src) {
    asm volatile("cp.async.cg.shared.global [%0], [%1], 16;\n" :: "r"(dst), "l"(src));
}
__device__ __forceinline__ void cpa_commit() { asm volatile("cp.async.commit_group;\n"); }
template <int N> __device__ __forceinline__ void cpa_wait() {
    asm volatile("cp.async.wait_group %0;\n" :: "n"(N));
}

// tile [16 k][128 n] from row-major [k][ld] -> S[k][136]
__device__ __forceinline__ void cpa_B16(float (*S)[136], const float* src, size_t ld, int tid) {
    int r = tid >> 5, c4 = (tid & 31) * 4;
    #pragma unroll
    for (int p = 0; p < 2; p++) {
        uint32_t d = (uint32_t)__cvta_generic_to_shared(&S[r + p * 8][c4]);
        cpa16(d, src + (size_t)(r + p * 8) * ld + c4);
    }
}
// tile [128 m][16 k] from row-major [m][ld] -> S[m][20]
__device__ __forceinline__ void cpa_A16(float (*S)[20], const float* src, size_t ld, int tid) {
    int m = tid >> 2, k4 = (tid & 3) * 4;
    #pragma unroll
    for (int p = 0; p < 2; p++) {
        uint32_t d = (uint32_t)__cvta_generic_to_shared(&S[m + p * 64][k4]);
        cpa16(d, src + (size_t)(m + p * 64) * ld + k4);
    }
}

// compute on As[k][136] (both operands k-major), 16-deep
__device__ __forceinline__ void comp_kk(const float (*As)[136], const float (*Bs)[136],
                                        float acc[4][4][4], int wr, int wc, int lane) {
    int t = lane & 3, g = lane >> 2;
    #pragma unroll
    for (int ks = 0; ks < 16; ks += 8) {
        unsigned a[4][4], b[4][2];
        #pragma unroll
        for (int mi = 0; mi < 4; mi++) {
            int r = wr * 64 + mi * 16 + g;
            a[mi][0] = __float_as_uint(As[ks + t][r]);
            a[mi][1] = __float_as_uint(As[ks + t][r + 8]);
            a[mi][2] = __float_as_uint(As[ks + t + 4][r]);
            a[mi][3] = __float_as_uint(As[ks + t + 4][r + 8]);
        }
        #pragma unroll
        for (int ni = 0; ni < 4; ni++) {
            int c = wc * 32 + ni * 8 + g;
            b[ni][0] = __float_as_uint(Bs[ks + t][c]);
            b[ni][1] = __float_as_uint(Bs[ks + t + 4][c]);
        }
        #pragma unroll
        for (int mi = 0; mi < 4; mi++)
            #pragma unroll
            for (int ni = 0; ni < 4; ni++) mma8(acc[mi][ni], a[mi], b[ni]);
    }
}

// compute on Am[m][20] (A m-major), Bs[k][136], 16-deep
__device__ __forceinline__ void comp_mk(const float (*Am)[20], const float (*Bs)[136],
                                        float acc[4][4][4], int wr, int wc, int lane) {
    int t = lane & 3, g = lane >> 2;
    #pragma unroll
    for (int ks = 0; ks < 16; ks += 8) {
        unsigned a[4][4], b[4][2];
        #pragma unroll
        for (int mi = 0; mi < 4; mi++) {
            int r = wr * 64 + mi * 16 + g;
            a[mi][0] = __float_as_uint(Am[r][ks + t]);
            a[mi][1] = __float_as_uint(Am[r + 8][ks + t]);
            a[mi][2] = __float_as_uint(Am[r][ks + t + 4]);
            a[mi][3] = __float_as_uint(Am[r + 8][ks + t + 4]);
        }
        #pragma unroll
        for (int ni = 0; ni < 4; ni++) {
            int c = wc * 32 + ni * 8 + g;
            b[ni][0] = __float_as_uint(Bs[ks + t][c]);
            b[ni][1] = __float_as_uint(Bs[ks + t + 4][c]);
        }
        #pragma unroll
        for (int mi = 0; mi < 4; mi++)
            #pragma unroll
            for (int ni = 0; ni < 4; ni++) mma8(acc[mi][ni], a[mi], b[ni]);
    }
}

// ---------------- small kernels ----------------------------------------------
__global__ void round_w(const float* __restrict__ qw, const float* __restrict__ kw,
                        const float* __restrict__ vw, const float* __restrict__ gw) {
    int i = blockIdx.x * 256 + threadIdx.x;
    if (i >= D * D) return;
    g_wq[i] = tf32f(qw[i]); g_wk[i] = tf32f(kw[i]);
    g_wv[i] = tf32f(vw[i]); g_wg[i] = tf32f(gw[i]);
}

__global__ void ln_kernel(const float* __restrict__ zin,
                          const float* __restrict__ gamma,
                          const float* __restrict__ beta) {
    int warp = (blockIdx.x * blockDim.x + threadIdx.x) >> 5;
    int lane = threadIdx.x & 31;
    if (warp >= M_ROWS) return;
    float4 x = ((const float4*)(zin + (size_t)warp * D))[lane];
    float s = x.x + x.y + x.z + x.w;
    float ss = x.x * x.x + x.y * x.y + x.z * x.z + x.w * x.w;
    #pragma unroll
    for (int o = 16; o; o >>= 1) {
        s += __shfl_xor_sync(0xffffffffu, s, o);
        ss += __shfl_xor_sync(0xffffffffu, ss, o);
    }
    float mean = s * (1.0f / 128.0f);
    float var = ss * (1.0f / 128.0f) - mean * mean;
    float rstd = rsqrtf(var + 1e-5f);
    float4 gg = ((const float4*)gamma)[lane];
    float4 bb = ((const float4*)beta)[lane];
    float4 o;
    o.x = tf32f((x.x - mean) * rstd * gg.x + bb.x);
    o.y = tf32f((x.y - mean) * rstd * gg.y + bb.y);
    o.z = tf32f((x.z - mean) * rstd * gg.z + bb.z);
    o.w = tf32f((x.w - mean) * rstd * gg.w + bb.w);
    ((float4*)(g_z + (size_t)warp * D))[lane] = o;
}

// bias projection with inline LN (full fp32 precision, independent of g_z)
__global__ void biasproj_kernel(const float* __restrict__ zin,
                                const float* __restrict__ gamma,
                                const float* __restrict__ beta,
                                const float* __restrict__ bw,
                                const float* __restrict__ bb) {
    int warp = (blockIdx.x * blockDim.x + threadIdx.x) >> 5;
    int lane = threadIdx.x & 31;
    if (warp >= M_ROWS) return;
    float4 x = ((const float4*)(zin + (size_t)warp * D))[lane];
    float s = x.x + x.y + x.z + x.w;
    float ss = x.x * x.x + x.y * x.y + x.z * x.z + x.w * x.w;
    #pragma unroll
    for (int o = 16; o; o >>= 1) {
        s += __shfl_xor_sync(0xffffffffu, s, o);
        ss += __shfl_xor_sync(0xffffffffu, ss, o);
    }
    float mean = s * (1.0f / 128.0f);
    float var = ss * (1.0f / 128.0f) - mean * mean;
    float rstd = rsqrtf(var + 1e-5f);
    float4 gg = ((const float4*)gamma)[lane];
    float4 bv = ((const float4*)beta)[lane];
    float n[4];
    n[0] = (x.x - mean) * rstd * gg.x + bv.x;
    n[1] = (x.y - mean) * rstd * gg.y + bv.y;
    n[2] = (x.z - mean) * rstd * gg.z + bv.z;
    n[3] = (x.w - mean) * rstd * gg.w + bv.w;
    float a0 = 0, a1 = 0, a2 = 0, a3 = 0;
    #pragma unroll
    for (int j = 0; j < 4; j++) {
        float4 w = *(const float4*)(bw + (lane * 4 + j) * 4);
        a0 += n[j] * w.x; a1 += n[j] * w.y; a2 += n[j] * w.z; a3 += n[j] * w.w;
    }
    #pragma unroll
    for (int o = 16; o; o >>= 1) {
        a0 += __shfl_xor_sync(0xffffffffu, a0, o);
        a1 += __shfl_xor_sync(0xffffffffu, a1, o);
        a2 += __shfl_xor_sync(0xffffffffu, a2, o);
        a3 += __shfl_xor_sync(0xffffffffu, a3, o);
    }
    if (lane == 0) {
        float* p = g_bias + (size_t)warp * 4;
        p[0] = a0 + bb[0]; p[1] = a1 + bb[1];
        p[2] = a2 + bb[2]; p[3] = a3 + bb[3];
    }
}

// ---------------- fused q/k/v/g projections ----------------------------------
// grid (4, 2048): x = which weight, y = m-block
__global__ void __launch_bounds__(256, 2) proj_mma(
    const float* __restrict__ qb, const float* __restrict__ kb,
    const float* __restrict__ vb, const float* __restrict__ gb)
{
    __shared__ float As[2][128][20];   // 20480 B
    __shared__ float Bs[2][16][136];   // 17408 B
    int which = blockIdx.x;
    int m0 = blockIdx.y * 128;
    const float* W = which == 0 ? g_wq : which == 1 ? g_wk : which == 2 ? g_wv : g_wg;
    const float* Bv = which == 0 ? qb : which == 1 ? kb : which == 2 ? vb : gb;
    int tid = threadIdx.x, lane = tid & 31, wid = tid >> 5;
    int wr = wid >> 2, wc = wid & 3;
    float acc[4][4][4] = {};
    const float* Abase = g_z + (size_t)m0 * 128;
    cpa_A16(As[0], Abase, 128, tid);
    cpa_B16(Bs[0], W, 128, tid);
    cpa_commit();
    for (int i = 0; i < 8; i++) {
        if (i + 1 < 8) {
            cpa_A16(As[(i + 1) & 1], Abase + (i + 1) * 16, 128, tid);
            cpa_B16(Bs[(i + 1) & 1], W + (size_t)(i + 1) * 16 * 128, 128, tid);
        }
        cpa_commit();
        cpa_wait<1>();
        __syncthreads();
        comp_mk(As[i & 1], Bs[i & 1], acc, wr, wc, lane);
        __syncthreads();
    }
    int t = lane & 3, g = lane >> 2;
    int b = m0 >> 9;
    int l0 = m0 & 511;
    if (which < 2) {
        // q/k: write [h][bc][l] coalesced along l, staged transposed in smem
        float* dst = (which == 0) ? g_qT : g_kT;
        float (*S2)[132] = (float(*)[132])&As[0][0][0];  // 32*132*4 = 16896 B
        for (int j = 0; j < 4; j++) {
            __syncthreads();
            if (wc == j) {
                #pragma unroll
                for (int mi = 0; mi < 4; mi++) {
                    int r = wr * 64 + mi * 16 + g;
                    #pragma unroll
                    for (int ni = 0; ni < 4; ni++) {
                        int c = ni * 8 + t * 2;
                        float b0 = Bv[j * 32 + c], b1 = Bv[j * 32 + c + 1];
                        S2[c][r] = tf32f(acc[mi][ni][0] + b0);
                        S2[c + 1][r] = tf32f(acc[mi][ni][1] + b1);
                        S2[c][r + 8] = tf32f(acc[mi][ni][2] + b0);
                        S2[c + 1][r + 8] = tf32f(acc[mi][ni][3] + b1);
                    }
                }
            }
            __syncthreads();
            #pragma unroll
            for (int pass = 0; pass < 4; pass++) {
                int c = wid + pass * 8;
                int l4 = lane * 4;
                float4 v = *(float4*)&S2[c][l4];
                *(float4*)(dst + ((size_t)j * R_DIM + b * 32 + c) * 512 + l0 + l4) = v;
            }
        }
    } else if (which == 2) {
        // v: write [h][k2][bc] coalesced along bc
        float (*S1)[36] = (float(*)[36])&As[0][0][0];    // 128*36*4 = 18432 B
        for (int j = 0; j < 4; j++) {
            __syncthreads();
            if (wc == j) {
                #pragma unroll
                for (int mi = 0; mi < 4; mi++) {
                    int r = wr * 64 + mi * 16 + g;
                    #pragma unroll
                    for (int ni = 0; ni < 4; ni++) {
                        int c = ni * 8 + t * 2;
                        float b0 = Bv[j * 32 + c], b1 = Bv[j * 32 + c + 1];
                        S1[r][c] = tf32f(acc[mi][ni][0] + b0);
                        S1[r][c + 1] = tf32f(acc[mi][ni][1] + b1);
                        S1[r + 8][c] = tf32f(acc[mi][ni][2] + b0);
                        S1[r + 8][c + 1] = tf32f(acc[mi][ni][3] + b1);
                    }
                }
            }
            __syncthreads();
            #pragma unroll
            for (int pass = 0; pass < 4; pass++) {
                int row = (tid >> 3) + pass * 32;
                int c4 = (tid & 7) * 4;
                float4 v = *(float4*)&S1[row][c4];
                *(float4*)(g_vt + ((size_t)j * 512 + l0 + row) * R_DIM + b * 32 + c4) = v;
            }
        }
    } else {
        // gate: sigmoid, natural row-major layout
        #pragma unroll
        for (int mi = 0; mi < 4; mi++) {
            int r0 = m0 + wr * 64 + mi * 16 + g;
            #pragma unroll
            for (int ni = 0; ni < 4; ni++) {
                int c = wc * 32 + ni * 8 + t * 2;
                float b0 = Bv[c], b1 = Bv[c + 1];
                float2 v0 = make_float2(1.f / (1.f + __expf(-(acc[mi][ni][0] + b0))),
                                        1.f / (1.f + __expf(-(acc[mi][ni][1] + b1))));
                float2 v1 = make_float2(1.f / (1.f + __expf(-(acc[mi][ni][2] + b0))),
                                        1.f / (1.f + __expf(-(acc[mi][ni][3] + b1))));
                *(float2*)(g_sig + (size_t)r0 * 128 + c) = v0;
                *(float2*)(g_sig + (size_t)(r0 + 8) * 128 + c) = v1;
            }
        }
    }
}

// ---------------- logits: split-K=8 ------------------------------------------
// grid (4, 4, 32): x = k-block, y = l-block, z = h*8+sk
__global__ void __launch_bounds__(256, 2) att_mma() {
    __shared__ float As[2][16][136];
    __shared__ float Bs[2][16][136];
    int n0 = blockIdx.x * 128, m0 = blockIdx.y * 128;
    int h = blockIdx.z >> 3, sk = blockIdx.z & 7;
    int tid = threadIdx.x, lane = tid & 31, wid = tid >> 5;
    int wr = wid >> 2, wc = wid & 3;
    const float* Aq = g_qT + (size_t)h * R_DIM * 512 + (size_t)sk * 2048 * 512 + m0;
    const float* Bk = g_kT + (size_t)h * R_DIM * 512 + (size_t)sk * 2048 * 512 + n0;
    float acc[4][4][4] = {};
    const int iters = 2048 / 16;
    cpa_B16(As[0], Aq, 512, tid);
    cpa_B16(Bs[0], Bk, 512, tid);
    cpa_commit();
    for (int i = 0; i < iters; i++) {
        if (i + 1 < iters) {
            cpa_B16(As[(i + 1) & 1], Aq + (size_t)(i + 1) * 16 * 512, 512, tid);
            cpa_B16(Bs[(i + 1) & 1], Bk + (size_t)(i + 1) * 16 * 512, 512, tid);
        }
        cpa_commit();
        cpa_wait<1>();
        __syncthreads();
        comp_kk(As[i & 1], Bs[i & 1], acc, wr, wc, lane);
        __syncthreads();
    }
    int t = lane & 3, g = lane >> 2;
    float* outp = g_part + (size_t)blockIdx.z * LL;
    #pragma unroll
    for (int mi = 0; mi < 4; mi++) {
        int l = m0 + wr * 64 + mi * 16 + g;
        #pragma unroll
        for (int ni = 0; ni < 4; ni++) {
            int k = n0 + wc * 32 + ni * 8 + t * 2;
            *(float2*)(outp + (size_t)l * 512 + k) =
                make_float2(acc[mi][ni][0], acc[mi][ni][1]);
            *(float2*)(outp + (size_t)(l + 8) * 512 + k) =
                make_float2(acc[mi][ni][2], acc[mi][ni][3]);
        }
    }
}

// ---------------- split-K reduce + scale + bias + softmax --------------------
__global__ void softmax2(float scale) {
    __shared__ float red[4];
    int h = blockIdx.x >> 9, l = blockIdx.x & 511;
    int tth = threadIdx.x;
    int warp = tth >> 5, lane = tth & 31;
    int k = tth * 4;
    float4 x = make_float4(0.f, 0.f, 0.f, 0.f);
    #pragma unroll
    for (int sk = 0; sk < 8; sk++) {
        const float4 p = *(const float4*)(g_part +
            ((size_t)(h * 8 + sk) * 512 + l) * 512 + k);
        x.x += p.x; x.y += p.y; x.z += p.z; x.w += p.w;
    }
    const float* bp = g_bias + ((size_t)l * 512 + k) * 4 + h;
    x.x = x.x * scale + bp[0];
    x.y = x.y * scale + bp[4];
    x.z = x.z * scale + bp[8];
    x.w = x.w * scale + bp[12];
    float m = fmaxf(fmaxf(x.x, x.y), fmaxf(x.z, x.w));
    #pragma unroll
    for (int o = 16; o; o >>= 1) m = fmaxf(m, __shfl_xor_sync(0xffffffffu, m, o));
    if (lane == 0) red[warp] = m;
    __syncthreads();
    m = fmaxf(fmaxf(red[0], red[1]), fmaxf(red[2], red[3]));
    __syncthreads();
    x.x = expf(x.x - m); x.y = expf(x.y - m);
    x.z = expf(x.z - m); x.w = expf(x.w - m);
    float s = x.x + x.y + x.z + x.w;
    #pragma unroll
    for (int o = 16; o; o >>= 1) s += __shfl_xor_sync(0xffffffffu, s, o);
    if (lane == 0) red[warp] = s;
    __syncthreads();
    s = red[0] + red[1] + red[2] + red[3];
    float inv = 1.0f / s;
    x.x = tf32f(x.x * inv); x.y = tf32f(x.y * inv);
    x.z = tf32f(x.z * inv); x.w = tf32f(x.w * inv);
    *(float4*)(g_att + ((size_t)(h * 512 + l)) * 512 + k) = x;
}

// ---------------- O = att @ V ------------------------------------------------
// grid (128, 4, 4): x = bc-block, y = l-block, z = head
__global__ void __launch_bounds__(256, 2) o_mma() {
    __shared__ float As[2][128][20];
    __shared__ float Bs[2][16][136];
    int n0 = blockIdx.x * 128, m0 = blockIdx.y * 128, h = blockIdx.z;
    int tid = threadIdx.x, lane = tid & 31, wid = tid >> 5;
    int wr = wid >> 2, wc = wid & 3;
    const float* Aa = g_att + (size_t)h * LL + (size_t)m0 * 512;
    const float* Bv = g_vt + (size_t)h * L * R_DIM + n0;
    float acc[4][4][4] = {};
    const int iters = 512 / 16;
    cpa_A16(As[0], Aa, 512, tid);
    cpa_B16(Bs[0], Bv, R_DIM, tid);
    cpa_commit();
    for (int i = 0; i < iters; i++) {
        if (i + 1 < iters) {
            cpa_A16(As[(i + 1) & 1], Aa + (i + 1) * 16, 512, tid);
            cpa_B16(Bs[(i + 1) & 1], Bv + (size_t)(i + 1) * 16 * R_DIM, R_DIM, tid);
        }
        cpa_commit();
        cpa_wait<1>();
        __syncthreads();
        comp_mk(As[i & 1], Bs[i & 1], acc, wr, wc, lane);
        __syncthreads();
    }
    int t = lane & 3, g = lane >> 2;
    float* outp = g_o + (size_t)h * L * R_DIM;
    #pragma unroll
    for (int mi = 0; mi < 4; mi++) {
        int l = m0 + wr * 64 + mi * 16 + g;
        #pragma unroll
        for (int ni = 0; ni < 4; ni++) {
            int n = n0 + wc * 32 + ni * 8 + t * 2;
            *(float2*)(outp + (size_t)l * R_DIM + n) =
                make_float2(acc[mi][ni][0], acc[mi][ni][1]);
            *(float2*)(outp + (size_t)(l + 8) * R_DIM + n) =
                make_float2(acc[mi][ni][2], acc[mi][ni][3]);
        }
    }
}

// ---------------- final: gate * o, project by ow, + ob -----------------------
__global__ void __launch_bounds__(256, 2) out_mma(const float* __restrict__ ow,
                                                  const float* __restrict__ ob,
                                                  float* __restrict__ out) {
    __shared__ float As[16][136];
    __shared__ float Bs[16][136];
    int m0 = blockIdx.x * 128;
    int tid = threadIdx.x, lane = tid & 31, wid = tid >> 5;
    int wr = wid >> 2, wc = wid & 3;
    float acc[4][4][4] = {};
    for (int kt = 0; kt < 128; kt += 16) {
        #pragma unroll
        for (int i = 0; i < 2; i++) {
            int r = (tid >> 2) + i * 64;
            int rb = m0 + r;
            int b = rb >> 9, l = rb & 511;
            int k4 = (tid & 3) * 4;
            int n = kt + k4;
            int hh = n >> 5, c = n & 31;
            float4 vo = *(const float4*)(g_o + ((size_t)hh * 512 + l) * R_DIM + b * 32 + c);
            float4 vs = *(const float4*)(g_sig + (size_t)rb * 128 + n);
            As[k4 + 0][r] = tf32f(vo.x * vs.x);
            As[k4 + 1][r] = tf32f(vo.y * vs.y);
            As[k4 + 2][r] = tf32f(vo.z * vs.z);
            As[k4 + 3][r] = tf32f(vo.w * vs.w);
        }
        {
            int k = (tid >> 5), n4 = (tid & 31) * 4;
            #pragma unroll
            for (int i = 0; i < 2; i++) {
                float4 v = *(const float4*)(ow + (size_t)(kt + k + i * 8) * 128 + n4);
                float* row = &Bs[k + i * 8][n4];
                row[0] = tf32f(v.x); row[1] = tf32f(v.y);
                row[2] = tf32f(v.z); row[3] = tf32f(v.w);
            }
        }
        __syncthreads();
        int t = lane & 3, g = lane >> 2;
        #pragma unroll
        for (int ks = 0; ks < 16; ks += 8) {
            unsigned a[4][4], b[4][2];
            #pragma unroll
            for (int mi = 0; mi < 4; mi++) {
                int r = wr * 64 + mi * 16 + g;
                a[mi][0] = __float_as_uint(As[ks + t][r]);
                a[mi][1] = __float_as_uint(As[ks + t][r + 8]);
                a[mi][2] = __float_as_uint(As[ks + t + 4][r]);
                a[mi][3] = __float_as_uint(As[ks + t + 4][r + 8]);
            }
            #pragma unroll
            for (int ni = 0; ni < 4; ni++) {
                int c = wc * 32 + ni * 8 + g;
                b[ni][0] = __float_as_uint(Bs[ks + t][c]);
                b[ni][1] = __float_as_uint(Bs[ks + t + 4][c]);
            }
            #pragma unroll
            for (int mi = 0; mi < 4; mi++)
                #pragma unroll
                for (int ni = 0; ni < 4; ni++) mma8(acc[mi][ni], a[mi], b[ni]);
        }
        __syncthreads();
    }
    int t = lane & 3, g = lane >> 2;
    #pragma unroll
    for (int mi = 0; mi < 4; mi++) {
        int r0 = m0 + wr * 64 + mi * 16 + g;
        #pragma unroll
        for (int ni = 0; ni < 4; ni++) {
            int c = wc * 32 + ni * 8 + t * 2;
            float b0 = ob[c], b1 = ob[c + 1];
            *(float2*)(out + (size_t)r0 * 128 + c) =
                make_float2(acc[mi][ni][0] + b0, acc[mi][ni][1] + b1);
            *(float2*)(out + (size_t)(r0 + 8) * 128 + c) =
                make_float2(acc[mi][ni][2] + b0, acc[mi][ni][3] + b1);
        }
    }
}

// ---------------- launcher ---------------------------------------------------
extern "C" void kernel_launch(void* const* d_in, const int* in_sizes, int n_in,
                              void* d_out, int out_size) {
    const float* z_   = (const float*)d_in[0];
    const float* ln_g = (const float*)d_in[1];
    const float* ln_b = (const float*)d_in[2];
    const float* qw   = (const float*)d_in[3];
    const float* qb   = (const float*)d_in[4];
    const float* kw   = (const float*)d_in[5];
    const float* kb   = (const float*)d_in[6];
    const float* vw   = (const float*)d_in[7];
    const float* vb   = (const float*)d_in[8];
    const float* bw   = (const float*)d_in[9];
    const float* bb   = (const float*)d_in[10];
    const float* gw   = (const float*)d_in[11];
    const float* gb   = (const float*)d_in[12];
    const float* ow   = (const float*)d_in[13];
    const float* ob   = (const float*)d_in[14];
    float* out = (float*)d_out;

    round_w<<<(D * D + 255) / 256, 256>>>(qw, kw, vw, gw);
    ln_kernel<<<M_ROWS / 8, 256>>>(z_, ln_g, ln_b);
    biasproj_kernel<<<M_ROWS / 8, 256>>>(z_, ln_g, ln_b, bw, bb);
    proj_mma<<<dim3(4, 2048), 256>>>(qb, kb, vb, gb);

    float scale = 1.0f / (sqrtf((float)CC) * sqrtf((float)L));
    att_mma<<<dim3(4, 4, 32), 256>>>();
    softmax2<<<NH * L, 128>>>(scale);
    o_mma<<<dim3(128, 4, 4), 256>>>();
    out_mma<<<2048, 256>>>(ow, ob, out);
}

// round 6
// speedup vs baseline: 3.7158x; 1.0751x over previous
#include <cuda_runtime.h>
#include <stdint.h>
#include <math.h>

#define L 512
#define D 128
#define NH 4
#define CC 32
#define M_ROWS (L * L)          // 262144
#define R_DIM (L * CC)          // 16384
#define LL (L * L)

// ---------------- scratch ----------------------------------------------------
__device__ float g_z[M_ROWS * D];        // post-LN z (tf32-rounded), [rb, d]
__device__ float g_qm[NH * L * R_DIM];   // q [h][l][bc] tf32-rounded (m-major)
__device__ float g_kT[NH * R_DIM * L];   // k [h][bc][l] tf32-rounded (k-major)
__device__ float g_vt[NH * L * R_DIM];   // v [h][k2][bc] tf32-rounded
__device__ float g_sig[M_ROWS * D];      // sigmoid(z@gw+gb)
__device__ float g_bias[M_ROWS * NH];    // [(l*512+k), h]
__device__ float g_part[32 * LL];        // [h*8+sk][l][k] split-K partials
__device__ float g_att[NH * LL];         // [h][l][k] softmax probs (tf32-rounded)
__device__ float g_o[NH * L * R_DIM];    // [h][l][bc]
__device__ float g_wq[D * D], g_wk[D * D], g_wv[D * D], g_wg[D * D]; // tf32 weights

// ---------------- helpers ----------------------------------------------------
__device__ __forceinline__ unsigned tf32c(float x) {
    unsigned u; asm("cvt.rna.tf32.f32 %0, %1;" : "=r"(u) : "f"(x)); return u;
}
__device__ __forceinline__ float tf32f(float x) { return __uint_as_float(tf32c(x)); }

__device__ __forceinline__ void mma8(float* c, const unsigned* a, const unsigned* b) {
    asm volatile(
        "mma.sync.aligned.m16n8k8.row.col.f32.tf32.tf32.f32 "
        "{%0,%1,%2,%3},{%4,%5,%6,%7},{%8,%9},{%0,%1,%2,%3};"
        : "+f"(c[0]), "+f"(c[1]), "+f"(c[2]), "+f"(c[3])
        : "r"(a[0]), "r"(a[1]), "r"(a[2]), "r"(a[3]), "r"(b[0]), "r"(b[1]));
}

__device__ __forceinline__ void cpa16(uint32_t dst, const float* src) {
    asm volatile("cp.async.cg.shared.global [%0], [%1], 16;\n" :: "r"(dst), "l"(src));
}
__device__ __forceinline__ void cpa_commit() { asm volatile("cp.async.commit_group;\n"); }
template <int N> __device__ __forceinline__ void cpa_wait() {
    asm volatile("cp.async.wait_group %0;\n" :: "n"(N));
}

// A tile [128 m][32 k] from row-major [m][ld] -> S[m][36]
__device__ __forceinline__ void cpa_A32(float (*S)[36], const float* src, size_t ld, int tid) {
    #pragma unroll
    for (int p = 0; p < 4; p++) {
        int idx = p * 256 + tid;
        int row = idx >> 3, c4 = (idx & 7) * 4;
        uint32_t d = (uint32_t)__cvta_generic_to_shared(&S[row][c4]);
        cpa16(d, src + (size_t)row * ld + c4);
    }
}
// B tile [32 k][128 n] from row-major [k][ld] -> S[k][136]
__device__ __forceinline__ void cpa_B32(float (*S)[136], const float* src, size_t ld, int tid) {
    #pragma unroll
    for (int p = 0; p < 4; p++) {
        int idx = p * 256 + tid;
        int r = idx >> 5, c4 = (idx & 31) * 4;
        uint32_t d = (uint32_t)__cvta_generic_to_shared(&S[r][c4]);
        cpa16(d, src + (size_t)r * ld + c4);
    }
}

// compute: Am[m][36] (A m-major), Bs[k][136], 32-deep
__device__ __forceinline__ void comp32(const float (*Am)[36], const float (*Bs)[136],
                                       float acc[4][4][4], int wr, int wc, int lane) {
    int t = lane & 3, g = lane >> 2;
    #pragma unroll
    for (int ks = 0; ks < 32; ks += 8) {
        unsigned a[4][4], b[4][2];
        #pragma unroll
        for (int mi = 0; mi < 4; mi++) {
            int r = wr * 64 + mi * 16 + g;
            a[mi][0] = __float_as_uint(Am[r][ks + t]);
            a[mi][1] = __float_as_uint(Am[r + 8][ks + t]);
            a[mi][2] = __float_as_uint(Am[r][ks + t + 4]);
            a[mi][3] = __float_as_uint(Am[r + 8][ks + t + 4]);
        }
        #pragma unroll
        for (int ni = 0; ni < 4; ni++) {
            int c = wc * 32 + ni * 8 + g;
            b[ni][0] = __float_as_uint(Bs[ks + t][c]);
            b[ni][1] = __float_as_uint(Bs[ks + t + 4][c]);
        }
        #pragma unroll
        for (int mi = 0; mi < 4; mi++)
            #pragma unroll
            for (int ni = 0; ni < 4; ni++) mma8(acc[mi][ni], a[mi], b[ni]);
    }
}

#define DYN_SMEM ((3 * 128 * 36 + 3 * 32 * 136) * 4)   // 107520 B

// ---------------- small kernels ----------------------------------------------
__global__ void round_w(const float* __restrict__ qw, const float* __restrict__ kw,
                        const float* __restrict__ vw, const float* __restrict__ gw) {
    int i = blockIdx.x * 256 + threadIdx.x;
    if (i >= D * D) return;
    g_wq[i] = tf32f(qw[i]); g_wk[i] = tf32f(kw[i]);
    g_wv[i] = tf32f(vw[i]); g_wg[i] = tf32f(gw[i]);
}

__global__ void ln_kernel(const float* __restrict__ zin,
                          const float* __restrict__ gamma,
                          const float* __restrict__ beta) {
    int warp = (blockIdx.x * blockDim.x + threadIdx.x) >> 5;
    int lane = threadIdx.x & 31;
    if (warp >= M_ROWS) return;
    float4 x = ((const float4*)(zin + (size_t)warp * D))[lane];
    float s = x.x + x.y + x.z + x.w;
    float ss = x.x * x.x + x.y * x.y + x.z * x.z + x.w * x.w;
    #pragma unroll
    for (int o = 16; o; o >>= 1) {
        s += __shfl_xor_sync(0xffffffffu, s, o);
        ss += __shfl_xor_sync(0xffffffffu, ss, o);
    }
    float mean = s * (1.0f / 128.0f);
    float var = ss * (1.0f / 128.0f) - mean * mean;
    float rstd = rsqrtf(var + 1e-5f);
    float4 gg = ((const float4*)gamma)[lane];
    float4 bb = ((const float4*)beta)[lane];
    float4 o;
    o.x = tf32f((x.x - mean) * rstd * gg.x + bb.x);
    o.y = tf32f((x.y - mean) * rstd * gg.y + bb.y);
    o.z = tf32f((x.z - mean) * rstd * gg.z + bb.z);
    o.w = tf32f((x.w - mean) * rstd * gg.w + bb.w);
    ((float4*)(g_z + (size_t)warp * D))[lane] = o;
}

__global__ void biasproj_kernel(const float* __restrict__ zin,
                                const float* __restrict__ gamma,
                                const float* __restrict__ beta,
                                const float* __restrict__ bw,
                                const float* __restrict__ bb) {
    int warp = (blockIdx.x * blockDim.x + threadIdx.x) >> 5;
    int lane = threadIdx.x & 31;
    if (warp >= M_ROWS) return;
    float4 x = ((const float4*)(zin + (size_t)warp * D))[lane];
    float s = x.x + x.y + x.z + x.w;
    float ss = x.x * x.x + x.y * x.y + x.z * x.z + x.w * x.w;
    #pragma unroll
    for (int o = 16; o; o >>= 1) {
        s += __shfl_xor_sync(0xffffffffu, s, o);
        ss += __shfl_xor_sync(0xffffffffu, ss, o);
    }
    float mean = s * (1.0f / 128.0f);
    float var = ss * (1.0f / 128.0f) - mean * mean;
    float rstd = rsqrtf(var + 1e-5f);
    float4 gg = ((const float4*)gamma)[lane];
    float4 bv = ((const float4*)beta)[lane];
    float n[4];
    n[0] = (x.x - mean) * rstd * gg.x + bv.x;
    n[1] = (x.y - mean) * rstd * gg.y + bv.y;
    n[2] = (x.z - mean) * rstd * gg.z + bv.z;
    n[3] = (x.w - mean) * rstd * gg.w + bv.w;
    float a0 = 0, a1 = 0, a2 = 0, a3 = 0;
    #pragma unroll
    for (int j = 0; j < 4; j++) {
        float4 w = *(const float4*)(bw + (lane * 4 + j) * 4);
        a0 += n[j] * w.x; a1 += n[j] * w.y; a2 += n[j] * w.z; a3 += n[j] * w.w;
    }
    #pragma unroll
    for (int o = 16; o; o >>= 1) {
        a0 += __shfl_xor_sync(0xffffffffu, a0, o);
        a1 += __shfl_xor_sync(0xffffffffu, a1, o);
        a2 += __shfl_xor_sync(0xffffffffu, a2, o);
        a3 += __shfl_xor_sync(0xffffffffu, a3, o);
    }
    if (lane == 0) {
        float* p = g_bias + (size_t)warp * 4;
        p[0] = a0 + bb[0]; p[1] = a1 + bb[1];
        p[2] = a2 + bb[2]; p[3] = a3 + bb[3];
    }
}

// ---------------- fused q/k/v/g projections ----------------------------------
// grid (4, 2048): x = which weight, y = m-block
__global__ void __launch_bounds__(256, 2) proj_mma(
    const float* __restrict__ qb, const float* __restrict__ kb,
    const float* __restrict__ vb, const float* __restrict__ gb)
{
    extern __shared__ float sp[];
    float (*As)[36] = (float(*)[36])sp;                       // 3 stages x 128
    float (*Bs)[136] = (float(*)[136])(sp + 3 * 128 * 36);    // 3 stages x 32
    int which = blockIdx.x;
    int m0 = blockIdx.y * 128;
    const float* W = which == 0 ? g_wq : which == 1 ? g_wk : which == 2 ? g_wv : g_wg;
    const float* Bv = which == 0 ? qb : which == 1 ? kb : which == 2 ? vb : gb;
    int tid = threadIdx.x, lane = tid & 31, wid = tid >> 5;
    int wr = wid >> 2, wc = wid & 3;
    float acc[4][4][4] = {};
    const float* Abase = g_z + (size_t)m0 * 128;
    const int iters = 4;
    cpa_A32(As, Abase, 128, tid); cpa_B32(Bs, W, 128, tid); cpa_commit();
    cpa_A32(As + 128, Abase + 32, 128, tid);
    cpa_B32(Bs + 32, W + 32 * 128, 128, tid); cpa_commit();
    for (int i = 0; i < iters; i++) {
        cpa_wait<1>();
        __syncthreads();
        comp32(As + (i % 3) * 128, Bs + (i % 3) * 32, acc, wr, wc, lane);
        if (i + 2 < iters) {
            cpa_A32(As + ((i + 2) % 3) * 128, Abase + (i + 2) * 32, 128, tid);
            cpa_B32(Bs + ((i + 2) % 3) * 32, W + (size_t)(i + 2) * 32 * 128, 128, tid);
        }
        cpa_commit();
    }
    __syncthreads();
    int t = lane & 3, g = lane >> 2;
    int b = m0 >> 9;
    int l0 = m0 & 511;
    if (which == 0 || which == 2) {
        // q/v: [h][l or k2][bc] coalesced along bc
        float* dst = (which == 0) ? g_qm : g_vt;
        float (*S1)[36] = (float(*)[36])sp;   // 128 x 36
        for (int j = 0; j < 4; j++) {
            __syncthreads();
            if (wc == j) {
                #pragma unroll
                for (int mi = 0; mi < 4; mi++) {
                    int r = wr * 64 + mi * 16 + g;
                    #pragma unroll
                    for (int ni = 0; ni < 4; ni++) {
                        int c = ni * 8 + t * 2;
                        float b0 = Bv[j * 32 + c], b1 = Bv[j * 32 + c + 1];
                        S1[r][c] = tf32f(acc[mi][ni][0] + b0);
                        S1[r][c + 1] = tf32f(acc[mi][ni][1] + b1);
                        S1[r + 8][c] = tf32f(acc[mi][ni][2] + b0);
                        S1[r + 8][c + 1] = tf32f(acc[mi][ni][3] + b1);
                    }
                }
            }
            __syncthreads();
            #pragma unroll
            for (int pass = 0; pass < 4; pass++) {
                int row = (tid >> 3) + pass * 32;
                int c4 = (tid & 7) * 4;
                float4 v = *(float4*)&S1[row][c4];
                *(float4*)(dst + ((size_t)j * 512 + l0 + row) * R_DIM + b * 32 + c4) = v;
            }
        }
    } else if (which == 1) {
        // k: [h][bc][l] coalesced along l, staged transposed
        float (*S2)[132] = (float(*)[132])sp;  // 32 x 132
        for (int j = 0; j < 4; j++) {
            __syncthreads();
            if (wc == j) {
                #pragma unroll
                for (int mi = 0; mi < 4; mi++) {
                    int r = wr * 64 + mi * 16 + g;
                    #pragma unroll
                    for (int ni = 0; ni < 4; ni++) {
                        int c = ni * 8 + t * 2;
                        float b0 = Bv[j * 32 + c], b1 = Bv[j * 32 + c + 1];
                        S2[c][r] = tf32f(acc[mi][ni][0] + b0);
                        S2[c + 1][r] = tf32f(acc[mi][ni][1] + b1);
                        S2[c][r + 8] = tf32f(acc[mi][ni][2] + b0);
                        S2[c + 1][r + 8] = tf32f(acc[mi][ni][3] + b1);
                    }
                }
            }
            __syncthreads();
            #pragma unroll
            for (int pass = 0; pass < 4; pass++) {
                int c = wid + pass * 8;
                int l4 = lane * 4;
                float4 v = *(float4*)&S2[c][l4];
                *(float4*)(g_kT + ((size_t)j * R_DIM + b * 32 + c) * 512 + l0 + l4) = v;
            }
        }
    } else {
        // gate: sigmoid, natural row-major
        #pragma unroll
        for (int mi = 0; mi < 4; mi++) {
            int r0 = m0 + wr * 64 + mi * 16 + g;
            #pragma unroll
            for (int ni = 0; ni < 4; ni++) {
                int c = wc * 32 + ni * 8 + t * 2;
                float b0 = Bv[c], b1 = Bv[c + 1];
                float2 v0 = make_float2(1.f / (1.f + __expf(-(acc[mi][ni][0] + b0))),
                                        1.f / (1.f + __expf(-(acc[mi][ni][1] + b1))));
                float2 v1 = make_float2(1.f / (1.f + __expf(-(acc[mi][ni][2] + b0))),
                                        1.f / (1.f + __expf(-(acc[mi][ni][3] + b1))));
                *(float2*)(g_sig + (size_t)r0 * 128 + c) = v0;
                *(float2*)(g_sig + (size_t)(r0 + 8) * 128 + c) = v1;
            }
        }
    }
}

// ---------------- logits: split-K=8 ------------------------------------------
// grid (4, 4, 32): x = k-block, y = l-block, z = h*8+sk
__global__ void __launch_bounds__(256, 2) att_mma() {
    extern __shared__ float sp[];
    float (*As)[36] = (float(*)[36])sp;
    float (*Bs)[136] = (float(*)[136])(sp + 3 * 128 * 36);
    int n0 = blockIdx.x * 128, m0 = blockIdx.y * 128;
    int h = blockIdx.z >> 3, sk = blockIdx.z & 7;
    int tid = threadIdx.x, lane = tid & 31, wid = tid >> 5;
    int wr = wid >> 2, wc = wid & 3;
    // A = q m-major [l][bc], slice cols [sk*2048, +2048)
    const float* Aq = g_qm + (size_t)h * L * R_DIM + (size_t)m0 * R_DIM + (size_t)sk * 2048;
    // B = k k-major [bc][kpos], slice rows [sk*2048, +2048)
    const float* Bk = g_kT + (size_t)h * R_DIM * 512 + (size_t)sk * 2048 * 512 + n0;
    float acc[4][4][4] = {};
    const int iters = 2048 / 32;
    cpa_A32(As, Aq, R_DIM, tid); cpa_B32(Bs, Bk, 512, tid); cpa_commit();
    cpa_A32(As + 128, Aq + 32, R_DIM, tid);
    cpa_B32(Bs + 32, Bk + (size_t)32 * 512, 512, tid); cpa_commit();
    for (int i = 0; i < iters; i++) {
        cpa_wait<1>();
        __syncthreads();
        comp32(As + (i % 3) * 128, Bs + (i % 3) * 32, acc, wr, wc, lane);
        if (i + 2 < iters) {
            cpa_A32(As + ((i + 2) % 3) * 128, Aq + (i + 2) * 32, R_DIM, tid);
            cpa_B32(Bs + ((i + 2) % 3) * 32, Bk + (size_t)(i + 2) * 32 * 512, 512, tid);
        }
        cpa_commit();
    }
    int t = lane & 3, g = lane >> 2;
    float* outp = g_part + (size_t)blockIdx.z * LL;
    #pragma unroll
    for (int mi = 0; mi < 4; mi++) {
        int l = m0 + wr * 64 + mi * 16 + g;
        #pragma unroll
        for (int ni = 0; ni < 4; ni++) {
            int k = n0 + wc * 32 + ni * 8 + t * 2;
            *(float2*)(outp + (size_t)l * 512 + k) =
                make_float2(acc[mi][ni][0], acc[mi][ni][1]);
            *(float2*)(outp + (size_t)(l + 8) * 512 + k) =
                make_float2(acc[mi][ni][2], acc[mi][ni][3]);
        }
    }
}

// ---------------- split-K reduce + scale + bias + softmax --------------------
__global__ void softmax2(float scale) {
    __shared__ float red[4];
    int h = blockIdx.x >> 9, l = blockIdx.x & 511;
    int tth = threadIdx.x;
    int warp = tth >> 5, lane = tth & 31;
    int k = tth * 4;
    float4 x = make_float4(0.f, 0.f, 0.f, 0.f);
    #pragma unroll
    for (int sk = 0; sk < 8; sk++) {
        const float4 p = *(const float4*)(g_part +
            ((size_t)(h * 8 + sk) * 512 + l) * 512 + k);
        x.x += p.x; x.y += p.y; x.z += p.z; x.w += p.w;
    }
    const float* bp = g_bias + ((size_t)l * 512 + k) * 4 + h;
    x.x = x.x * scale + bp[0];
    x.y = x.y * scale + bp[4];
    x.z = x.z * scale + bp[8];
    x.w = x.w * scale + bp[12];
    float m = fmaxf(fmaxf(x.x, x.y), fmaxf(x.z, x.w));
    #pragma unroll
    for (int o = 16; o; o >>= 1) m = fmaxf(m, __shfl_xor_sync(0xffffffffu, m, o));
    if (lane == 0) red[warp] = m;
    __syncthreads();
    m = fmaxf(fmaxf(red[0], red[1]), fmaxf(red[2], red[3]));
    __syncthreads();
    x.x = expf(x.x - m); x.y = expf(x.y - m);
    x.z = expf(x.z - m); x.w = expf(x.w - m);
    float s = x.x + x.y + x.z + x.w;
    #pragma unroll
    for (int o = 16; o; o >>= 1) s += __shfl_xor_sync(0xffffffffu, s, o);
    if (lane == 0) red[warp] = s;
    __syncthreads();
    s = red[0] + red[1] + red[2] + red[3];
    float inv = 1.0f / s;
    x.x = tf32f(x.x * inv); x.y = tf32f(x.y * inv);
    x.z = tf32f(x.z * inv); x.w = tf32f(x.w * inv);
    *(float4*)(g_att + ((size_t)(h * 512 + l)) * 512 + k) = x;
}

// ---------------- O = att @ V ------------------------------------------------
// grid (128, 4, 4): x = bc-block, y = l-block, z = head
__global__ void __launch_bounds__(256, 2) o_mma() {
    extern __shared__ float sp[];
    float (*As)[36] = (float(*)[36])sp;
    float (*Bs)[136] = (float(*)[136])(sp + 3 * 128 * 36);
    int n0 = blockIdx.x * 128, m0 = blockIdx.y * 128, h = blockIdx.z;
    int tid = threadIdx.x, lane = tid & 31, wid = tid >> 5;
    int wr = wid >> 2, wc = wid & 3;
    const float* Aa = g_att + (size_t)h * LL + (size_t)m0 * 512;
    const float* Bv = g_vt + (size_t)h * L * R_DIM + n0;
    float acc[4][4][4] = {};
    const int iters = 512 / 32;
    cpa_A32(As, Aa, 512, tid); cpa_B32(Bs, Bv, R_DIM, tid); cpa_commit();
    cpa_A32(As + 128, Aa + 32, 512, tid);
    cpa_B32(Bs + 32, Bv + (size_t)32 * R_DIM, R_DIM, tid); cpa_commit();
    for (int i = 0; i < iters; i++) {
        cpa_wait<1>();
        __syncthreads();
        comp32(As + (i % 3) * 128, Bs + (i % 3) * 32, acc, wr, wc, lane);
        if (i + 2 < iters) {
            cpa_A32(As + ((i + 2) % 3) * 128, Aa + (i + 2) * 32, 512, tid);
            cpa_B32(Bs + ((i + 2) % 3) * 32, Bv + (size_t)(i + 2) * 32 * R_DIM, R_DIM, tid);
        }
        cpa_commit();
    }
    int t = lane & 3, g = lane >> 2;
    float* outp = g_o + (size_t)h * L * R_DIM;
    #pragma unroll
    for (int mi = 0; mi < 4; mi++) {
        int l = m0 + wr * 64 + mi * 16 + g;
        #pragma unroll
        for (int ni = 0; ni < 4; ni++) {
            int n = n0 + wc * 32 + ni * 8 + t * 2;
            *(float2*)(outp + (size_t)l * R_DIM + n) =
                make_float2(acc[mi][ni][0], acc[mi][ni][1]);
            *(float2*)(outp + (size_t)(l + 8) * R_DIM + n) =
                make_float2(acc[mi][ni][2], acc[mi][ni][3]);
        }
    }
}

// ---------------- final: gate * o, project by ow, + ob -----------------------
__global__ void __launch_bounds__(256, 2) out_mma(const float* __restrict__ ow,
                                                  const float* __restrict__ ob,
                                                  float* __restrict__ out) {
    __shared__ float As[16][136];
    __shared__ float Bs[16][136];
    int m0 = blockIdx.x * 128;
    int tid = threadIdx.x, lane = tid & 31, wid = tid >> 5;
    int wr = wid >> 2, wc = wid & 3;
    float acc[4][4][4] = {};
    for (int kt = 0; kt < 128; kt += 16) {
        #pragma unroll
        for (int i = 0; i < 2; i++) {
            int r = (tid >> 2) + i * 64;
            int rb = m0 + r;
            int b = rb >> 9, l = rb & 511;
            int k4 = (tid & 3) * 4;
            int n = kt + k4;
            int hh = n >> 5, c = n & 31;
            float4 vo = *(const float4*)(g_o + ((size_t)hh * 512 + l) * R_DIM + b * 32 + c);
            float4 vs = *(const float4*)(g_sig + (size_t)rb * 128 + n);
            As[k4 + 0][r] = tf32f(vo.x * vs.x);
            As[k4 + 1][r] = tf32f(vo.y * vs.y);
            As[k4 + 2][r] = tf32f(vo.z * vs.z);
            As[k4 + 3][r] = tf32f(vo.w * vs.w);
        }
        {
            int k = (tid >> 5), n4 = (tid & 31) * 4;
            #pragma unroll
            for (int i = 0; i < 2; i++) {
                float4 v = *(const float4*)(ow + (size_t)(kt + k + i * 8) * 128 + n4);
                float* row = &Bs[k + i * 8][n4];
                row[0] = tf32f(v.x); row[1] = tf32f(v.y);
                row[2] = tf32f(v.z); row[3] = tf32f(v.w);
            }
        }
        __syncthreads();
        int t = lane & 3, g = lane >> 2;
        #pragma unroll
        for (int ks = 0; ks < 16; ks += 8) {
            unsigned a[4][4], b[4][2];
            #pragma unroll
            for (int mi = 0; mi < 4; mi++) {
                int r = wr * 64 + mi * 16 + g;
                a[mi][0] = __float_as_uint(As[ks + t][r]);
                a[mi][1] = __float_as_uint(As[ks + t][r + 8]);
                a[mi][2] = __float_as_uint(As[ks + t + 4][r]);
                a[mi][3] = __float_as_uint(As[ks + t + 4][r + 8]);
            }
            #pragma unroll
            for (int ni = 0; ni < 4; ni++) {
                int c = wc * 32 + ni * 8 + g;
                b[ni][0] = __float_as_uint(Bs[ks + t][c]);
                b[ni][1] = __float_as_uint(Bs[ks + t + 4][c]);
            }
            #pragma unroll
            for (int mi = 0; mi < 4; mi++)
                #pragma unroll
                for (int ni = 0; ni < 4; ni++) mma8(acc[mi][ni], a[mi], b[ni]);
        }
        __syncthreads();
    }
    int t = lane & 3, g = lane >> 2;
    #pragma unroll
    for (int mi = 0; mi < 4; mi++) {
        int r0 = m0 + wr * 64 + mi * 16 + g;
        #pragma unroll
        for (int ni = 0; ni < 4; ni++) {
            int c = wc * 32 + ni * 8 + t * 2;
            float b0 = ob[c], b1 = ob[c + 1];
            *(float2*)(out + (size_t)r0 * 128 + c) =
                make_float2(acc[mi][ni][0] + b0, acc[mi][ni][1] + b1);
            *(float2*)(out + (size_t)(r0 + 8) * 128 + c) =
                make_float2(acc[mi][ni][2] + b0, acc[mi][ni][3] + b1);
        }
    }
}

// ---------------- launcher ---------------------------------------------------
extern "C" void kernel_launch(void* const* d_in, const int* in_sizes, int n_in,
                              void* d_out, int out_size) {
    const float* z_   = (const float*)d_in[0];
    const float* ln_g = (const float*)d_in[1];
    const float* ln_b = (const float*)d_in[2];
    const float* qw   = (const float*)d_in[3];
    const float* qb   = (const float*)d_in[4];
    const float* kw   = (const float*)d_in[5];
    const float* kb   = (const float*)d_in[6];
    const float* vw   = (const float*)d_in[7];
    const float* vb   = (const float*)d_in[8];
    const float* bw   = (const float*)d_in[9];
    const float* bb   = (const float*)d_in[10];
    const float* gw   = (const float*)d_in[11];
    const float* gb   = (const float*)d_in[12];
    const float* ow   = (const float*)d_in[13];
    const float* ob   = (const float*)d_in[14];
    float* out = (float*)d_out;

    cudaFuncSetAttribute(proj_mma, cudaFuncAttributeMaxDynamicSharedMemorySize, DYN_SMEM);
    cudaFuncSetAttribute(att_mma, cudaFuncAttributeMaxDynamicSharedMemorySize, DYN_SMEM);
    cudaFuncSetAttribute(o_mma, cudaFuncAttributeMaxDynamicSharedMemorySize, DYN_SMEM);

    round_w<<<(D * D + 255) / 256, 256>>>(qw, kw, vw, gw);
    ln_kernel<<<M_ROWS / 8, 256>>>(z_, ln_g, ln_b);
    biasproj_kernel<<<M_ROWS / 8, 256>>>(z_, ln_g, ln_b, bw, bb);
    proj_mma<<<dim3(4, 2048), 256, DYN_SMEM>>>(qb, kb, vb, gb);

    float scale = 1.0f / (sqrtf((float)CC) * sqrtf((float)L));
    att_mma<<<dim3(4, 4, 32), 256, DYN_SMEM>>>();
    softmax2<<<NH * L, 128>>>(scale);
    o_mma<<<dim3(128, 4, 4), 256, DYN_SMEM>>>();
    out_mma<<<2048, 256>>>(ow, ob, out);
}

// round 7
// speedup vs baseline: 3.8158x; 1.0269x over previous
#include <cuda_runtime.h>
#include <stdint.h>
#include <math.h>

#define L 512
#define D 128
#define NH 4
#define CC 32
#define M_ROWS (L * L)          // 262144
#define R_DIM (L * CC)          // 16384
#define LL (L * L)

// ---------------- scratch ----------------------------------------------------
__device__ float g_z[M_ROWS * D];        // post-LN z (tf32-rounded), [rb, d]
__device__ float g_qm[NH * L * R_DIM];   // q [h][l][bc] tf32-rounded (m-major)
__device__ float g_kT[NH * R_DIM * L];   // k [h][bc][l] tf32-rounded (k-major)
__device__ float g_vt[NH * L * R_DIM];   // v [h][k2][bc] tf32-rounded
__device__ float g_sig[M_ROWS * D];      // sigmoid(z@gw+gb)
__device__ float g_bias[M_ROWS * NH];    // [(l*512+k), h]
__device__ float g_part[32 * LL];        // [h*8+sk][l][k] split-K partials
__device__ float g_att[NH * LL];         // [h][l][k] softmax probs (tf32-rounded)
__device__ float g_o[NH * L * R_DIM];    // [h][l][bc]  (gated + tf32-rounded)
__device__ float g_wq[D * D], g_wk[D * D], g_wv[D * D], g_wg[D * D], g_wo[D * D];

// ---------------- helpers ----------------------------------------------------
__device__ __forceinline__ unsigned tf32c(float x) {
    unsigned u; asm("cvt.rna.tf32.f32 %0, %1;" : "=r"(u) : "f"(x)); return u;
}
__device__ __forceinline__ float tf32f(float x) { return __uint_as_float(tf32c(x)); }

__device__ __forceinline__ void mma8(float* c, const unsigned* a, const unsigned* b) {
    asm volatile(
        "mma.sync.aligned.m16n8k8.row.col.f32.tf32.tf32.f32 "
        "{%0,%1,%2,%3},{%4,%5,%6,%7},{%8,%9},{%0,%1,%2,%3};"
        : "+f"(c[0]), "+f"(c[1]), "+f"(c[2]), "+f"(c[3])
        : "r"(a[0]), "r"(a[1]), "r"(a[2]), "r"(a[3]), "r"(b[0]), "r"(b[1]));
}

__device__ __forceinline__ void cpa16(uint32_t dst, const float* src) {
    asm volatile("cp.async.cg.shared.global [%0], [%1], 16;\n" :: "r"(dst), "l"(src));
}
__device__ __forceinline__ void cpa_commit() { asm volatile("cp.async.commit_group;\n"); }
template <int N> __device__ __forceinline__ void cpa_wait() {
    asm volatile("cp.async.wait_group %0;\n" :: "n"(N));
}

// A tile [128 m][32 k] from row-major [m][ld] -> S[m][36]
__device__ __forceinline__ void cpa_A32(float (*S)[36], const float* src, size_t ld, int tid) {
    #pragma unroll
    for (int p = 0; p < 4; p++) {
        int idx = p * 256 + tid;
        int row = idx >> 3, c4 = (idx & 7) * 4;
        uint32_t d = (uint32_t)__cvta_generic_to_shared(&S[row][c4]);
        cpa16(d, src + (size_t)row * ld + c4);
    }
}
// B tile [32 k][128 n] from row-major [k][ld] -> S[k][136]
__device__ __forceinline__ void cpa_B32(float (*S)[136], const float* src, size_t ld, int tid) {
    #pragma unroll
    for (int p = 0; p < 4; p++) {
        int idx = p * 256 + tid;
        int r = idx >> 5, c4 = (idx & 31) * 4;
        uint32_t d = (uint32_t)__cvta_generic_to_shared(&S[r][c4]);
        cpa16(d, src + (size_t)r * ld + c4);
    }
}

// compute: Am[m][36] (A m-major), Bs[k][136], 32-deep
__device__ __forceinline__ void comp32(const float (*Am)[36], const float (*Bs)[136],
                                       float acc[4][4][4], int wr, int wc, int lane) {
    int t = lane & 3, g = lane >> 2;
    #pragma unroll
    for (int ks = 0; ks < 32; ks += 8) {
        unsigned a[4][4], b[4][2];
        #pragma unroll
        for (int mi = 0; mi < 4; mi++) {
            int r = wr * 64 + mi * 16 + g;
            a[mi][0] = __float_as_uint(Am[r][ks + t]);
            a[mi][1] = __float_as_uint(Am[r + 8][ks + t]);
            a[mi][2] = __float_as_uint(Am[r][ks + t + 4]);
            a[mi][3] = __float_as_uint(Am[r + 8][ks + t + 4]);
        }
        #pragma unroll
        for (int ni = 0; ni < 4; ni++) {
            int c = wc * 32 + ni * 8 + g;
            b[ni][0] = __float_as_uint(Bs[ks + t][c]);
            b[ni][1] = __float_as_uint(Bs[ks + t + 4][c]);
        }
        #pragma unroll
        for (int mi = 0; mi < 4; mi++)
            #pragma unroll
            for (int ni = 0; ni < 4; ni++) mma8(acc[mi][ni], a[mi], b[ni]);
    }
}

#define DYN_SMEM ((3 * 128 * 36 + 3 * 32 * 136) * 4)   // 107520 B

// ---------------- small kernels ----------------------------------------------
__global__ void round_w(const float* __restrict__ qw, const float* __restrict__ kw,
                        const float* __restrict__ vw, const float* __restrict__ gw,
                        const float* __restrict__ ow) {
    int i = blockIdx.x * 256 + threadIdx.x;
    if (i >= D * D) return;
    g_wq[i] = tf32f(qw[i]); g_wk[i] = tf32f(kw[i]);
    g_wv[i] = tf32f(vw[i]); g_wg[i] = tf32f(gw[i]);
    g_wo[i] = tf32f(ow[i]);
}

__global__ void ln_kernel(const float* __restrict__ zin,
                          const float* __restrict__ gamma,
                          const float* __restrict__ beta) {
    int warp = (blockIdx.x * blockDim.x + threadIdx.x) >> 5;
    int lane = threadIdx.x & 31;
    if (warp >= M_ROWS) return;
    float4 x = ((const float4*)(zin + (size_t)warp * D))[lane];
    float s = x.x + x.y + x.z + x.w;
    float ss = x.x * x.x + x.y * x.y + x.z * x.z + x.w * x.w;
    #pragma unroll
    for (int o = 16; o; o >>= 1) {
        s += __shfl_xor_sync(0xffffffffu, s, o);
        ss += __shfl_xor_sync(0xffffffffu, ss, o);
    }
    float mean = s * (1.0f / 128.0f);
    float var = ss * (1.0f / 128.0f) - mean * mean;
    float rstd = rsqrtf(var + 1e-5f);
    float4 gg = ((const float4*)gamma)[lane];
    float4 bb = ((const float4*)beta)[lane];
    float4 o;
    o.x = tf32f((x.x - mean) * rstd * gg.x + bb.x);
    o.y = tf32f((x.y - mean) * rstd * gg.y + bb.y);
    o.z = tf32f((x.z - mean) * rstd * gg.z + bb.z);
    o.w = tf32f((x.w - mean) * rstd * gg.w + bb.w);
    ((float4*)(g_z + (size_t)warp * D))[lane] = o;
}

__global__ void biasproj_kernel(const float* __restrict__ zin,
                                const float* __restrict__ gamma,
                                const float* __restrict__ beta,
                                const float* __restrict__ bw,
                                const float* __restrict__ bb) {
    int warp = (blockIdx.x * blockDim.x + threadIdx.x) >> 5;
    int lane = threadIdx.x & 31;
    if (warp >= M_ROWS) return;
    float4 x = ((const float4*)(zin + (size_t)warp * D))[lane];
    float s = x.x + x.y + x.z + x.w;
    float ss = x.x * x.x + x.y * x.y + x.z * x.z + x.w * x.w;
    #pragma unroll
    for (int o = 16; o; o >>= 1) {
        s += __shfl_xor_sync(0xffffffffu, s, o);
        ss += __shfl_xor_sync(0xffffffffu, ss, o);
    }
    float mean = s * (1.0f / 128.0f);
    float var = ss * (1.0f / 128.0f) - mean * mean;
    float rstd = rsqrtf(var + 1e-5f);
    float4 gg = ((const float4*)gamma)[lane];
    float4 bv = ((const float4*)beta)[lane];
    float n[4];
    n[0] = (x.x - mean) * rstd * gg.x + bv.x;
    n[1] = (x.y - mean) * rstd * gg.y + bv.y;
    n[2] = (x.z - mean) * rstd * gg.z + bv.z;
    n[3] = (x.w - mean) * rstd * gg.w + bv.w;
    float a0 = 0, a1 = 0, a2 = 0, a3 = 0;
    #pragma unroll
    for (int j = 0; j < 4; j++) {
        float4 w = *(const float4*)(bw + (lane * 4 + j) * 4);
        a0 += n[j] * w.x; a1 += n[j] * w.y; a2 += n[j] * w.z; a3 += n[j] * w.w;
    }
    #pragma unroll
    for (int o = 16; o; o >>= 1) {
        a0 += __shfl_xor_sync(0xffffffffu, a0, o);
        a1 += __shfl_xor_sync(0xffffffffu, a1, o);
        a2 += __shfl_xor_sync(0xffffffffu, a2, o);
        a3 += __shfl_xor_sync(0xffffffffu, a3, o);
    }
    if (lane == 0) {
        float* p = g_bias + (size_t)warp * 4;
        p[0] = a0 + bb[0]; p[1] = a1 + bb[1];
        p[2] = a2 + bb[2]; p[3] = a3 + bb[3];
    }
}

// ---------------- fused q/k/v/g projections ----------------------------------
// grid (4, 2048): x = which weight, y = m-block
__global__ void __launch_bounds__(256, 2) proj_mma(
    const float* __restrict__ qb, const float* __restrict__ kb,
    const float* __restrict__ vb, const float* __restrict__ gb)
{
    extern __shared__ float sp[];
    float (*As)[36] = (float(*)[36])sp;
    float (*Bs)[136] = (float(*)[136])(sp + 3 * 128 * 36);
    int which = blockIdx.x;
    int m0 = blockIdx.y * 128;
    const float* W = which == 0 ? g_wq : which == 1 ? g_wk : which == 2 ? g_wv : g_wg;
    const float* Bv = which == 0 ? qb : which == 1 ? kb : which == 2 ? vb : gb;
    int tid = threadIdx.x, lane = tid & 31, wid = tid >> 5;
    int wr = wid >> 2, wc = wid & 3;
    float acc[4][4][4] = {};
    const float* Abase = g_z + (size_t)m0 * 128;
    const int iters = 4;
    cpa_A32(As, Abase, 128, tid); cpa_B32(Bs, W, 128, tid); cpa_commit();
    cpa_A32(As + 128, Abase + 32, 128, tid);
    cpa_B32(Bs + 32, W + 32 * 128, 128, tid); cpa_commit();
    for (int i = 0; i < iters; i++) {
        cpa_wait<1>();
        __syncthreads();
        comp32(As + (i % 3) * 128, Bs + (i % 3) * 32, acc, wr, wc, lane);
        if (i + 2 < iters) {
            cpa_A32(As + ((i + 2) % 3) * 128, Abase + (i + 2) * 32, 128, tid);
            cpa_B32(Bs + ((i + 2) % 3) * 32, W + (size_t)(i + 2) * 32 * 128, 128, tid);
        }
        cpa_commit();
    }
    __syncthreads();     // done with As/Bs; reuse as stage
    int t = lane & 3, g = lane >> 2;
    int b = m0 >> 9;
    int l0 = m0 & 511;
    float (*S)[132] = (float(*)[132])sp;   // 128 x 132 stage (69.6KB incl pad? 67.5KB)

    if (which != 1) {
        // row-major stage: S[r][c], all warps at once
        #pragma unroll
        for (int mi = 0; mi < 4; mi++) {
            int r = wr * 64 + mi * 16 + g;
            #pragma unroll
            for (int ni = 0; ni < 4; ni++) {
                int c = wc * 32 + ni * 8 + t * 2;
                if (which == 3) {
                    float b0 = Bv[c], b1 = Bv[c + 1];
                    *(float2*)&S[r][c] = make_float2(
                        1.f / (1.f + __expf(-(acc[mi][ni][0] + b0))),
                        1.f / (1.f + __expf(-(acc[mi][ni][1] + b1))));
                    *(float2*)&S[r + 8][c] = make_float2(
                        1.f / (1.f + __expf(-(acc[mi][ni][2] + b0))),
                        1.f / (1.f + __expf(-(acc[mi][ni][3] + b1))));
                } else {
                    float b0 = Bv[c], b1 = Bv[c + 1];
                    *(float2*)&S[r][c] = make_float2(tf32f(acc[mi][ni][0] + b0),
                                                     tf32f(acc[mi][ni][1] + b1));
                    *(float2*)&S[r + 8][c] = make_float2(tf32f(acc[mi][ni][2] + b0),
                                                         tf32f(acc[mi][ni][3] + b1));
                }
            }
        }
        __syncthreads();
        if (which == 3) {
            #pragma unroll
            for (int p = 0; p < 16; p++) {
                int idx = p * 256 + tid;
                int row = idx >> 5, c4 = (idx & 31) * 4;
                *(float4*)(g_sig + (size_t)(m0 + row) * 128 + c4) = *(float4*)&S[row][c4];
            }
        } else {
            float* dst = (which == 0) ? g_qm : g_vt;
            #pragma unroll
            for (int p = 0; p < 16; p++) {
                int idx = p * 256 + tid;
                int row = idx >> 5, c4 = (idx & 31) * 4;
                int hh = c4 >> 5, cc = c4 & 31;
                *(float4*)(dst + ((size_t)hh * 512 + l0 + row) * R_DIM + b * 32 + cc) =
                    *(float4*)&S[row][c4];
            }
        }
    } else {
        // k: transposed stage S[c][r], then coalesced along l
        #pragma unroll
        for (int mi = 0; mi < 4; mi++) {
            int r = wr * 64 + mi * 16 + g;
            #pragma unroll
            for (int ni = 0; ni < 4; ni++) {
                int c = wc * 32 + ni * 8 + t * 2;
                float b0 = Bv[c], b1 = Bv[c + 1];
                S[c][r] = tf32f(acc[mi][ni][0] + b0);
                S[c + 1][r] = tf32f(acc[mi][ni][1] + b1);
                S[c][r + 8] = tf32f(acc[mi][ni][2] + b0);
                S[c + 1][r + 8] = tf32f(acc[mi][ni][3] + b1);
            }
        }
        __syncthreads();
        #pragma unroll
        for (int p = 0; p < 16; p++) {
            int idx = p * 256 + tid;
            int c = idx >> 5, l4 = (idx & 31) * 4;
            *(float4*)(g_kT + ((size_t)(c >> 5) * R_DIM + b * 32 + (c & 31)) * 512 + l0 + l4) =
                *(float4*)&S[c][l4];
        }
    }
}

// ---------------- logits: split-K=8 ------------------------------------------
// grid (4, 4, 32): x = k-block, y = l-block, z = h*8+sk
__global__ void __launch_bounds__(256, 2) att_mma() {
    extern __shared__ float sp[];
    float (*As)[36] = (float(*)[36])sp;
    float (*Bs)[136] = (float(*)[136])(sp + 3 * 128 * 36);
    int n0 = blockIdx.x * 128, m0 = blockIdx.y * 128;
    int h = blockIdx.z >> 3, sk = blockIdx.z & 7;
    int tid = threadIdx.x, lane = tid & 31, wid = tid >> 5;
    int wr = wid >> 2, wc = wid & 3;
    const float* Aq = g_qm + (size_t)h * L * R_DIM + (size_t)m0 * R_DIM + (size_t)sk * 2048;
    const float* Bk = g_kT + (size_t)h * R_DIM * 512 + (size_t)sk * 2048 * 512 + n0;
    float acc[4][4][4] = {};
    const int iters = 2048 / 32;
    cpa_A32(As, Aq, R_DIM, tid); cpa_B32(Bs, Bk, 512, tid); cpa_commit();
    cpa_A32(As + 128, Aq + 32, R_DIM, tid);
    cpa_B32(Bs + 32, Bk + (size_t)32 * 512, 512, tid); cpa_commit();
    for (int i = 0; i < iters; i++) {
        cpa_wait<1>();
        __syncthreads();
        comp32(As + (i % 3) * 128, Bs + (i % 3) * 32, acc, wr, wc, lane);
        if (i + 2 < iters) {
            cpa_A32(As + ((i + 2) % 3) * 128, Aq + (i + 2) * 32, R_DIM, tid);
            cpa_B32(Bs + ((i + 2) % 3) * 32, Bk + (size_t)(i + 2) * 32 * 512, 512, tid);
        }
        cpa_commit();
    }
    int t = lane & 3, g = lane >> 2;
    float* outp = g_part + (size_t)blockIdx.z * LL;
    #pragma unroll
    for (int mi = 0; mi < 4; mi++) {
        int l = m0 + wr * 64 + mi * 16 + g;
        #pragma unroll
        for (int ni = 0; ni < 4; ni++) {
            int k = n0 + wc * 32 + ni * 8 + t * 2;
            *(float2*)(outp + (size_t)l * 512 + k) =
                make_float2(acc[mi][ni][0], acc[mi][ni][1]);
            *(float2*)(outp + (size_t)(l + 8) * 512 + k) =
                make_float2(acc[mi][ni][2], acc[mi][ni][3]);
        }
    }
}

// ---------------- split-K reduce + scale + bias + softmax --------------------
__global__ void softmax2(float scale) {
    __shared__ float red[4];
    int h = blockIdx.x >> 9, l = blockIdx.x & 511;
    int tth = threadIdx.x;
    int warp = tth >> 5, lane = tth & 31;
    int k = tth * 4;
    float4 x = make_float4(0.f, 0.f, 0.f, 0.f);
    #pragma unroll
    for (int sk = 0; sk < 8; sk++) {
        const float4 p = *(const float4*)(g_part +
            ((size_t)(h * 8 + sk) * 512 + l) * 512 + k);
        x.x += p.x; x.y += p.y; x.z += p.z; x.w += p.w;
    }
    const float* bp = g_bias + ((size_t)l * 512 + k) * 4 + h;
    x.x = x.x * scale + bp[0];
    x.y = x.y * scale + bp[4];
    x.z = x.z * scale + bp[8];
    x.w = x.w * scale + bp[12];
    float m = fmaxf(fmaxf(x.x, x.y), fmaxf(x.z, x.w));
    #pragma unroll
    for (int o = 16; o; o >>= 1) m = fmaxf(m, __shfl_xor_sync(0xffffffffu, m, o));
    if (lane == 0) red[warp] = m;
    __syncthreads();
    m = fmaxf(fmaxf(red[0], red[1]), fmaxf(red[2], red[3]));
    __syncthreads();
    x.x = expf(x.x - m); x.y = expf(x.y - m);
    x.z = expf(x.z - m); x.w = expf(x.w - m);
    float s = x.x + x.y + x.z + x.w;
    #pragma unroll
    for (int o = 16; o; o >>= 1) s += __shfl_xor_sync(0xffffffffu, s, o);
    if (lane == 0) red[warp] = s;
    __syncthreads();
    s = red[0] + red[1] + red[2] + red[3];
    float inv = 1.0f / s;
    x.x = tf32f(x.x * inv); x.y = tf32f(x.y * inv);
    x.z = tf32f(x.z * inv); x.w = tf32f(x.w * inv);
    *(float4*)(g_att + ((size_t)(h * 512 + l)) * 512 + k) = x;
}

// ---------------- O = att @ V, fused gating in epilogue ----------------------
// grid (128, 4, 4): x = bc-block, y = l-block, z = head
__global__ void __launch_bounds__(256, 2) o_mma() {
    extern __shared__ float sp[];
    float (*As)[36] = (float(*)[36])sp;
    float (*Bs)[136] = (float(*)[136])(sp + 3 * 128 * 36);
    int n0 = blockIdx.x * 128, m0 = blockIdx.y * 128, h = blockIdx.z;
    int tid = threadIdx.x, lane = tid & 31, wid = tid >> 5;
    int wr = wid >> 2, wc = wid & 3;
    const float* Aa = g_att + (size_t)h * LL + (size_t)m0 * 512;
    const float* Bv = g_vt + (size_t)h * L * R_DIM + n0;
    float acc[4][4][4] = {};
    const int iters = 512 / 32;
    cpa_A32(As, Aa, 512, tid); cpa_B32(Bs, Bv, R_DIM, tid); cpa_commit();
    cpa_A32(As + 128, Aa + 32, 512, tid);
    cpa_B32(Bs + 32, Bv + (size_t)32 * R_DIM, R_DIM, tid); cpa_commit();
    for (int i = 0; i < iters; i++) {
        cpa_wait<1>();
        __syncthreads();
        comp32(As + (i % 3) * 128, Bs + (i % 3) * 32, acc, wr, wc, lane);
        if (i + 2 < iters) {
            cpa_A32(As + ((i + 2) % 3) * 128, Aa + (i + 2) * 32, 512, tid);
            cpa_B32(Bs + ((i + 2) % 3) * 32, Bv + (size_t)(i + 2) * 32 * R_DIM, R_DIM, tid);
        }
        cpa_commit();
    }
    int t = lane & 3, g = lane >> 2;
    float* outp = g_o + (size_t)h * L * R_DIM;
    #pragma unroll
    for (int mi = 0; mi < 4; mi++) {
        int l = m0 + wr * 64 + mi * 16 + g;
        #pragma unroll
        for (int ni = 0; ni < 4; ni++) {
            int n = n0 + wc * 32 + ni * 8 + t * 2;
            int bb = n >> 5, cc = n & 31;
            const float* sig0 = g_sig + ((size_t)bb * 512 + l) * 128 + h * 32 + cc;
            float2 s0 = *(const float2*)sig0;
            float2 s1 = *(const float2*)(sig0 + (size_t)8 * R_DIM * 0 + 8 * 128); // l+8 row
            *(float2*)(outp + (size_t)l * R_DIM + n) =
                make_float2(tf32f(acc[mi][ni][0] * s0.x), tf32f(acc[mi][ni][1] * s0.y));
            *(float2*)(outp + (size_t)(l + 8) * R_DIM + n) =
                make_float2(tf32f(acc[mi][ni][2] * s1.x), tf32f(acc[mi][ni][3] * s1.y));
        }
    }
}

// ---------------- final: out = g_o @ ow + ob (pipelined) ---------------------
// grid (2048)
__global__ void __launch_bounds__(256, 2) out_mma(const float* __restrict__ ob,
                                                  float* __restrict__ out) {
    extern __shared__ float sp[];
    float (*As)[36] = (float(*)[36])sp;
    float (*Bs)[136] = (float(*)[136])(sp + 3 * 128 * 36);
    int m0 = blockIdx.x * 128;
    int b = m0 >> 9, l0 = m0 & 511;
    int tid = threadIdx.x, lane = tid & 31, wid = tid >> 5;
    int wr = wid >> 2, wc = wid & 3;
    float acc[4][4][4] = {};
    const int iters = 4;
    // A-tile for k-tile i comes from head i: g_o[i][l0+r][b*32 + kk]
    #define OUT_APTR(i) (g_o + ((size_t)(i) * 512 + l0) * R_DIM + b * 32)
    cpa_A32(As, OUT_APTR(0), R_DIM, tid);
    cpa_B32(Bs, g_wo, 128, tid); cpa_commit();
    cpa_A32(As + 128, OUT_APTR(1), R_DIM, tid);
    cpa_B32(Bs + 32, g_wo + 32 * 128, 128, tid); cpa_commit();
    for (int i = 0; i < iters; i++) {
        cpa_wait<1>();
        __syncthreads();
        comp32(As + (i % 3) * 128, Bs + (i % 3) * 32, acc, wr, wc, lane);
        if (i + 2 < iters) {
            cpa_A32(As + ((i + 2) % 3) * 128, OUT_APTR(i + 2), R_DIM, tid);
            cpa_B32(Bs + ((i + 2) % 3) * 32, g_wo + (size_t)(i + 2) * 32 * 128, 128, tid);
        }
        cpa_commit();
    }
    #undef OUT_APTR
    int t = lane & 3, g = lane >> 2;
    #pragma unroll
    for (int mi = 0; mi < 4; mi++) {
        int r0 = m0 + wr * 64 + mi * 16 + g;
        #pragma unroll
        for (int ni = 0; ni < 4; ni++) {
            int c = wc * 32 + ni * 8 + t * 2;
            float b0 = ob[c], b1 = ob[c + 1];
            *(float2*)(out + (size_t)r0 * 128 + c) =
                make_float2(acc[mi][ni][0] + b0, acc[mi][ni][1] + b1);
            *(float2*)(out + (size_t)(r0 + 8) * 128 + c) =
                make_float2(acc[mi][ni][2] + b0, acc[mi][ni][3] + b1);
        }
    }
}

// ---------------- launcher ---------------------------------------------------
extern "C" void kernel_launch(void* const* d_in, const int* in_sizes, int n_in,
                              void* d_out, int out_size) {
    const float* z_   = (const float*)d_in[0];
    const float* ln_g = (const float*)d_in[1];
    const float* ln_b = (const float*)d_in[2];
    const float* qw   = (const float*)d_in[3];
    const float* qb   = (const float*)d_in[4];
    const float* kw   = (const float*)d_in[5];
    const float* kb   = (const float*)d_in[6];
    const float* vw   = (const float*)d_in[7];
    const float* vb   = (const float*)d_in[8];
    const float* bw   = (const float*)d_in[9];
    const float* bb   = (const float*)d_in[10];
    const float* gw   = (const float*)d_in[11];
    const float* gb   = (const float*)d_in[12];
    const float* ow   = (const float*)d_in[13];
    const float* ob   = (const float*)d_in[14];
    float* out = (float*)d_out;

    cudaFuncSetAttribute(proj_mma, cudaFuncAttributeMaxDynamicSharedMemorySize, DYN_SMEM);
    cudaFuncSetAttribute(att_mma, cudaFuncAttributeMaxDynamicSharedMemorySize, DYN_SMEM);
    cudaFuncSetAttribute(o_mma, cudaFuncAttributeMaxDynamicSharedMemorySize, DYN_SMEM);
    cudaFuncSetAttribute(out_mma, cudaFuncAttributeMaxDynamicSharedMemorySize, DYN_SMEM);

    round_w<<<(D * D + 255) / 256, 256>>>(qw, kw, vw, gw, ow);
    ln_kernel<<<M_ROWS / 8, 256>>>(z_, ln_g, ln_b);
    biasproj_kernel<<<M_ROWS / 8, 256>>>(z_, ln_g, ln_b, bw, bb);
    proj_mma<<<dim3(4, 2048), 256, DYN_SMEM>>>(qb, kb, vb, gb);

    float scale = 1.0f / (sqrtf((float)CC) * sqrtf((float)L));
    att_mma<<<dim3(4, 4, 32), 256, DYN_SMEM>>>();
    softmax2<<<NH * L, 128>>>(scale);
    o_mma<<<dim3(128, 4, 4), 256, DYN_SMEM>>>();
    out_mma<<<2048, 256, DYN_SMEM>>>(ob, out);
}